// round 1
// baseline (speedup 1.0000x reference)
#include <cuda_runtime.h>
#include <cuda_bf16.h>
#include <cstdint>

// Problem constants
#define NMAX   50000
#define DD     128
#define NRELMX 237

// ---------------- static device scratch (no allocations allowed) ------------
__device__ float g_C[(size_t)NMAX * 256];   // GEMM out: [:,0:128]=X@W_I^T, [:,128:256]=X@W_O^T
__device__ float g_Y[(size_t)NMAX * DD];    // X@W_I^T (needed for edge scatter)
__device__ float g_H[(size_t)NMAX * DD];    // layer-1 hidden accumulator
__device__ float g_W[DD * 256];             // packed weights, k-major [k][n]
__device__ float g_R[NRELMX * DD];          // rel @ W_I^T

// ---------------- pack weights: W[k][n] = n<128 ? W_I[n][k] : W_O[n-128][k] --
__global__ void packw_kernel(const float* __restrict__ W_I,
                             const float* __restrict__ W_O) {
    int idx = blockIdx.x * blockDim.x + threadIdx.x;
    if (idx >= DD * 256) return;
    int k = idx >> 8;
    int n = idx & 255;
    g_W[idx] = (n < DD) ? W_I[n * DD + k] : W_O[(n - DD) * DD + k];
}

// ---------------- R[r][n] = sum_k rel[r][k] * W_I[n][k] ---------------------
__global__ void relgemm_kernel(const float* __restrict__ rel,
                               const float* __restrict__ W_I) {
    __shared__ float rr[DD];
    int r = blockIdx.x;
    int n = threadIdx.x;
    rr[n] = rel[r * DD + n];
    __syncthreads();
    const float4* w4 = (const float4*)(W_I + n * DD);
    float s = 0.f;
#pragma unroll
    for (int kk = 0; kk < DD / 4; kk++) {
        float4 wv = w4[kk];
        s += rr[4 * kk + 0] * wv.x + rr[4 * kk + 1] * wv.y +
             rr[4 * kk + 2] * wv.z + rr[4 * kk + 3] * wv.w;
    }
    g_R[r * DD + n] = s;
}

// ---------------- main GEMM: C[M,256] = A[M,128] @ g_W[128,256] -------------
// BM=128, BN=128 (grid.y=2 covers N=256), BK=16, 256 threads, 8x8 per thread
// with split halves (rows {ty*4, 64+ty*4}, cols {tx*4, 64+tx*4}) for
// conflict-free float4 LDS.
template <bool RELU, bool FROM_H>
__global__ __launch_bounds__(256) void gemm_kernel(const float* __restrict__ Ain, int M) {
    __shared__ float As[16][132];
    __shared__ float Bs[16][132];
    const float* A = FROM_H ? g_H : Ain;

    int bm = blockIdx.x * 128;
    int bn = blockIdx.y * 128;
    int tid = threadIdx.x;
    int tx = tid & 15;
    int ty = tid >> 4;

    float acc[8][8];
#pragma unroll
    for (int i = 0; i < 8; i++)
#pragma unroll
        for (int j = 0; j < 8; j++) acc[i][j] = 0.f;

    for (int k0 = 0; k0 < DD; k0 += 16) {
        // A tile load: 128 rows x 16 cols = 512 float4 slots, 2 per thread
#pragma unroll
        for (int i = 0; i < 2; i++) {
            int slot = tid + i * 256;
            int row = slot >> 2;
            int c4 = (slot & 3) * 4;
            int gm = bm + row;
            float4 v = make_float4(0.f, 0.f, 0.f, 0.f);
            if (gm < M) v = *(const float4*)(A + (size_t)gm * DD + k0 + c4);
            if (RELU) {
                v.x = fmaxf(v.x, 0.f); v.y = fmaxf(v.y, 0.f);
                v.z = fmaxf(v.z, 0.f); v.w = fmaxf(v.w, 0.f);
            }
            As[c4 + 0][row] = v.x;
            As[c4 + 1][row] = v.y;
            As[c4 + 2][row] = v.z;
            As[c4 + 3][row] = v.w;
        }
        // B tile load: 16 rows x 128 cols = 512 float4 slots, 2 per thread
#pragma unroll
        for (int i = 0; i < 2; i++) {
            int slot = tid + i * 256;
            int row = slot >> 5;
            int c4 = (slot & 31) * 4;
            float4 v = *(const float4*)(&g_W[(k0 + row) * 256 + bn + c4]);
            *(float4*)&Bs[row][c4] = v;
        }
        __syncthreads();
#pragma unroll
        for (int k = 0; k < 16; k++) {
            float4 a0 = *(const float4*)&As[k][ty * 4];
            float4 a1 = *(const float4*)&As[k][64 + ty * 4];
            float4 b0 = *(const float4*)&Bs[k][tx * 4];
            float4 b1 = *(const float4*)&Bs[k][64 + tx * 4];
            float ra[8] = {a0.x, a0.y, a0.z, a0.w, a1.x, a1.y, a1.z, a1.w};
            float rb[8] = {b0.x, b0.y, b0.z, b0.w, b1.x, b1.y, b1.z, b1.w};
#pragma unroll
            for (int i = 0; i < 8; i++)
#pragma unroll
                for (int j = 0; j < 8; j++) acc[i][j] += ra[i] * rb[j];
        }
        __syncthreads();
    }

#pragma unroll
    for (int hi = 0; hi < 2; hi++) {
#pragma unroll
        for (int i = 0; i < 4; i++) {
            int gm = bm + hi * 64 + ty * 4 + i;
            if (gm >= M) continue;
            int ii = hi * 4 + i;
            float4 v0 = make_float4(acc[ii][0], acc[ii][1], acc[ii][2], acc[ii][3]);
            float4 v1 = make_float4(acc[ii][4], acc[ii][5], acc[ii][6], acc[ii][7]);
            *(float4*)(&g_C[(size_t)gm * 256 + bn + tx * 4]) = v0;
            *(float4*)(&g_C[(size_t)gm * 256 + bn + 64 + tx * 4]) = v1;
        }
    }
}

// ---------------- init: Y = C[:, :128]; H = Y + C[:,128:] - R[0] + b --------
template <bool TO_OUT>
__global__ void init_kernel(const float* __restrict__ b, float* __restrict__ extout, int M) {
    int idx = blockIdx.x * blockDim.x + threadIdx.x;  // one float4 per thread
    int total = M * (DD / 4);
    if (idx >= total) return;
    int m = idx >> 5;          // /32 float4 per row
    int n4 = (idx & 31) * 4;
    float4 y = *(const float4*)&g_C[(size_t)m * 256 + n4];
    float4 z = *(const float4*)&g_C[(size_t)m * 256 + DD + n4];
    float4 r0 = *(const float4*)&g_R[n4];
    float4 bb = *(const float4*)&b[n4];
    *(float4*)&g_Y[(size_t)m * DD + n4] = y;
    float4 h = make_float4(y.x + z.x - r0.x + bb.x,
                           y.y + z.y - r0.y + bb.y,
                           y.z + z.z - r0.z + bb.z,
                           y.w + z.w - r0.w + bb.w);
    float* H = TO_OUT ? extout : g_H;
    *(float4*)&H[(size_t)m * DD + n4] = h;
}

// ---------------- scatter: H[dst] += Y[src] - R[etype], one warp/edge -------
template <bool TO_OUT>
__global__ __launch_bounds__(256) void scatter_kernel(const int* __restrict__ src,
                                                      const int* __restrict__ dst,
                                                      const int* __restrict__ et,
                                                      float* __restrict__ extout, int E) {
    int e = blockIdx.x * (blockDim.x >> 5) + (threadIdx.x >> 5);
    if (e >= E) return;
    int lane = threadIdx.x & 31;
    int s = __ldg(src + e);
    int d = __ldg(dst + e);
    int t = __ldg(et + e);
    float4 y = *(const float4*)&g_Y[(size_t)s * DD + lane * 4];
    float4 r = *(const float4*)&g_R[(size_t)t * DD + lane * 4];
    float4 v = make_float4(y.x - r.x, y.y - r.y, y.z - r.z, y.w - r.w);
    float* H = TO_OUT ? extout : g_H;
    float* p = H + (size_t)d * DD + lane * 4;
    asm volatile("red.global.add.v4.f32 [%0], {%1,%2,%3,%4};"
                 :: "l"(p), "f"(v.x), "f"(v.y), "f"(v.z), "f"(v.w)
                 : "memory");
}

// ---------------------------------------------------------------------------
extern "C" void kernel_launch(void* const* d_in, const int* in_sizes, int n_in,
                              void* d_out, int out_size) {
    const float* x    = (const float*)d_in[0];
    const int*   ei   = (const int*)d_in[1];
    const int*   et   = (const int*)d_in[2];
    const float* W_I1 = (const float*)d_in[3];
    const float* W_O1 = (const float*)d_in[4];
    const float* rel1 = (const float*)d_in[5];
    const float* b1   = (const float*)d_in[6];
    const float* W_I2 = (const float*)d_in[7];
    const float* W_O2 = (const float*)d_in[8];
    const float* rel2 = (const float*)d_in[9];
    const float* b2   = (const float*)d_in[10];
    float* out = (float*)d_out;

    int M = in_sizes[0] / DD;      // 50000
    int E = in_sizes[2];           // 800000
    const int* src = ei;
    const int* dst = ei + E;

    dim3 ggemm((M + 127) / 128, 2);
    int init_blocks = (M * (DD / 4) + 255) / 256;
    int scat_blocks = (E + 7) / 8;   // 8 warps / block

    // ---- layer 1 ----
    packw_kernel<<<(DD * 256 + 255) / 256, 256>>>(W_I1, W_O1);
    relgemm_kernel<<<NRELMX, DD>>>(rel1, W_I1);
    gemm_kernel<false, false><<<ggemm, 256>>>(x, M);
    init_kernel<false><<<init_blocks, 256>>>(b1, nullptr, M);
    scatter_kernel<false><<<scat_blocks, 256>>>(src, dst, et, nullptr, E);

    // ---- layer 2 (ReLU folded into GEMM A-load) ----
    packw_kernel<<<(DD * 256 + 255) / 256, 256>>>(W_I2, W_O2);
    relgemm_kernel<<<NRELMX, DD>>>(rel2, W_I2);
    gemm_kernel<true, true><<<ggemm, 256>>>(nullptr, M);
    init_kernel<true><<<init_blocks, 256>>>(b2, out, M);
    scatter_kernel<true><<<scat_blocks, 256>>>(src, dst, et, out, E);
}

// round 2
// speedup vs baseline: 1.2023x; 1.2023x over previous
#include <cuda_runtime.h>
#include <cuda_bf16.h>
#include <cstdint>

#define NMAX   50000
#define EMAX   800000
#define DD     128
#define NRELMX 237

// ---------------- static device scratch ------------------------------------
__device__ float g_Y[(size_t)NMAX * DD];      // X@W_I^T (for edge gather)
__device__ float g_H[(size_t)NMAX * DD];      // layer-1 hidden
__device__ float g_W[DD * 256];               // packed weights, k-major [k][n]
__device__ float g_R[NRELMX * DD];            // rel @ W_I^T
__device__ int   g_cnt[NMAX];                 // per-dst degree
__device__ int   g_fill[NMAX];                // fill cursors
__device__ int   g_rowstart[NMAX + 1];        // CSR row starts
__device__ int2  g_edata[EMAX];               // sorted (src, etype) per edge

// ---------------- f32x2 helpers ---------------------------------------------
__device__ __forceinline__ unsigned long long fma2(unsigned long long a,
                                                   unsigned long long b,
                                                   unsigned long long c) {
    unsigned long long d;
    asm("fma.rn.f32x2 %0, %1, %2, %3;" : "=l"(d) : "l"(a), "l"(b), "l"(c));
    return d;
}
__device__ __forceinline__ unsigned long long bcast2(float x) {
    unsigned long long d;
    unsigned int xi = __float_as_uint(x);
    asm("mov.b64 %0, {%1, %2};" : "=l"(d) : "r"(xi), "r"(xi));
    return d;
}
__device__ __forceinline__ float2 unpack2(unsigned long long v) {
    float2 r;
    asm("mov.b64 {%0, %1}, %2;" : "=f"(r.x), "=f"(r.y) : "l"(v));
    return r;
}

// ---------------- pack weights: W[k][n] = n<128 ? W_I[n][k] : W_O[n-128][k] --
__global__ void packw_kernel(const float* __restrict__ W_I,
                             const float* __restrict__ W_O) {
    int idx = blockIdx.x * blockDim.x + threadIdx.x;
    if (idx >= DD * 256) return;
    int k = idx >> 8;
    int n = idx & 255;
    g_W[idx] = (n < DD) ? W_I[n * DD + k] : W_O[(n - DD) * DD + k];
}

// ---------------- R[r][n] = sum_k rel[r][k] * W_I[n][k] ---------------------
__global__ void relgemm_kernel(const float* __restrict__ rel,
                               const float* __restrict__ W_I) {
    __shared__ float rr[DD];
    int r = blockIdx.x;
    int n = threadIdx.x;
    rr[n] = rel[r * DD + n];
    __syncthreads();
    const float4* w4 = (const float4*)(W_I + n * DD);
    float s = 0.f;
#pragma unroll
    for (int kk = 0; kk < DD / 4; kk++) {
        float4 wv = w4[kk];
        s += rr[4 * kk + 0] * wv.x + rr[4 * kk + 1] * wv.y +
             rr[4 * kk + 2] * wv.z + rr[4 * kk + 3] * wv.w;
    }
    g_R[r * DD + n] = s;
}

// ---------------- edge sort: histogram / scan / fill ------------------------
__global__ void zero_kernel(int M) {
    int i = blockIdx.x * blockDim.x + threadIdx.x;
    if (i < M) { g_cnt[i] = 0; g_fill[i] = 0; }
}
__global__ void hist_kernel(const int* __restrict__ dst, int E) {
    int e = blockIdx.x * blockDim.x + threadIdx.x;
    if (e < E) atomicAdd(&g_cnt[dst[e]], 1);
}
__global__ __launch_bounds__(1024) void scan_kernel(int M) {
    __shared__ int ssum[1024];
    int t = threadIdx.x;
    const int CH = (M + 1023) / 1024;
    int beg = t * CH;
    int s = 0;
    for (int i = 0; i < CH; i++) {
        int idx = beg + i;
        if (idx < M) s += g_cnt[idx];
    }
    ssum[t] = s;
    __syncthreads();
    for (int off = 1; off < 1024; off <<= 1) {
        int v = (t >= off) ? ssum[t - off] : 0;
        __syncthreads();
        ssum[t] += v;
        __syncthreads();
    }
    int pre = (t == 0) ? 0 : ssum[t - 1];
    for (int i = 0; i < CH; i++) {
        int idx = beg + i;
        if (idx < M) {
            g_rowstart[idx] = pre;
            pre += g_cnt[idx];
        }
    }
    if (t == 1023) g_rowstart[M] = pre;
}
__global__ void fill_kernel(const int* __restrict__ src,
                            const int* __restrict__ dst,
                            const int* __restrict__ et, int E) {
    int e = blockIdx.x * blockDim.x + threadIdx.x;
    if (e >= E) return;
    int d = dst[e];
    int pos = g_rowstart[d] + atomicAdd(&g_fill[d], 1);
    g_edata[pos] = make_int2(src[e], et[e]);
}

// ---------------- fused GEMM: [Y|Z] = A @ g_W; H = Y+Z-R0+b; store Y,H ------
// BM=128, BN=256, BK=16, 512 threads; per thread 8 rows x 8 cols (4 f32x2)
template <bool RELU, bool FROM_H, bool TO_OUT>
__global__ __launch_bounds__(512) void gemm_fused_kernel(const float* __restrict__ Ain,
                                                         const float* __restrict__ bias,
                                                         float* __restrict__ extout, int M) {
    __shared__ float As[16][132];
    __shared__ float Bs[16][256];
    const float* A = FROM_H ? g_H : Ain;

    int bm = blockIdx.x * 128;
    int tid = threadIdx.x;
    int tx = tid & 31;
    int ty = tid >> 5;

    unsigned long long acc[8][4];
#pragma unroll
    for (int i = 0; i < 8; i++)
#pragma unroll
        for (int j = 0; j < 4; j++) acc[i][j] = 0ULL;

    for (int k0 = 0; k0 < DD; k0 += 16) {
        // A tile: 128 rows x 16 cols = 512 float4 slots, one per thread
        {
            int row = tid >> 2;
            int c4 = (tid & 3) * 4;
            int gm = bm + row;
            float4 v = make_float4(0.f, 0.f, 0.f, 0.f);
            if (gm < M) v = *(const float4*)(A + (size_t)gm * DD + k0 + c4);
            if (RELU) {
                v.x = fmaxf(v.x, 0.f); v.y = fmaxf(v.y, 0.f);
                v.z = fmaxf(v.z, 0.f); v.w = fmaxf(v.w, 0.f);
            }
            As[c4 + 0][row] = v.x;
            As[c4 + 1][row] = v.y;
            As[c4 + 2][row] = v.z;
            As[c4 + 3][row] = v.w;
        }
        // B tile: 16 rows x 256 cols = 1024 float4 slots, two per thread
#pragma unroll
        for (int i = 0; i < 2; i++) {
            int slot = tid + i * 512;
            int brow = slot >> 6;
            int bc4 = (slot & 63) * 4;
            *(float4*)&Bs[brow][bc4] = *(const float4*)&g_W[(k0 + brow) * 256 + bc4];
        }
        __syncthreads();
#pragma unroll
        for (int k = 0; k < 16; k++) {
            float4 a0 = *(const float4*)&As[k][ty * 4];
            float4 a1 = *(const float4*)&As[k][64 + ty * 4];
            ulonglong2 b0 = *(const ulonglong2*)&Bs[k][tx * 4];
            ulonglong2 b1 = *(const ulonglong2*)&Bs[k][128 + tx * 4];
            unsigned long long ap[8];
            ap[0] = bcast2(a0.x); ap[1] = bcast2(a0.y);
            ap[2] = bcast2(a0.z); ap[3] = bcast2(a0.w);
            ap[4] = bcast2(a1.x); ap[5] = bcast2(a1.y);
            ap[6] = bcast2(a1.z); ap[7] = bcast2(a1.w);
#pragma unroll
            for (int i = 0; i < 8; i++) {
                acc[i][0] = fma2(ap[i], b0.x, acc[i][0]);
                acc[i][1] = fma2(ap[i], b0.y, acc[i][1]);
                acc[i][2] = fma2(ap[i], b1.x, acc[i][2]);
                acc[i][3] = fma2(ap[i], b1.y, acc[i][3]);
            }
        }
        __syncthreads();
    }

    // epilogue: Y = low half, Z = high half; H = Y + Z - R0 + b
    int n4 = tx * 4;
    float4 r0 = *(const float4*)&g_R[n4];
    float4 bb = *(const float4*)&bias[n4];
    float* H = TO_OUT ? extout : g_H;
#pragma unroll
    for (int hi = 0; hi < 2; hi++) {
#pragma unroll
        for (int i = 0; i < 4; i++) {
            int gm = bm + hi * 64 + ty * 4 + i;
            if (gm >= M) continue;
            int ii = hi * 4 + i;
            float2 y01 = unpack2(acc[ii][0]);
            float2 y23 = unpack2(acc[ii][1]);
            float2 z01 = unpack2(acc[ii][2]);
            float2 z23 = unpack2(acc[ii][3]);
            float4 yv = make_float4(y01.x, y01.y, y23.x, y23.y);
            float4 hv = make_float4(yv.x + z01.x - r0.x + bb.x,
                                    yv.y + z01.y - r0.y + bb.y,
                                    yv.z + z23.x - r0.z + bb.z,
                                    yv.w + z23.y - r0.w + bb.w);
            *(float4*)&g_Y[(size_t)gm * DD + n4] = yv;
            *(float4*)&H[(size_t)gm * DD + n4] = hv;
        }
    }
}

// ---------------- gather: H[n] += sum over in-edges of (Y[src] - R[et]) -----
template <bool TO_OUT>
__global__ __launch_bounds__(256) void gather_kernel(float* __restrict__ extout, int M) {
    int node = blockIdx.x * 8 + (threadIdx.x >> 5);
    if (node >= M) return;
    int lane = threadIdx.x & 31;
    int off = lane * 4;
    int beg = g_rowstart[node];
    int end = g_rowstart[node + 1];
    float4 acc = make_float4(0.f, 0.f, 0.f, 0.f);
    int i = beg;
    for (; i + 1 < end; i += 2) {
        int2 e0 = __ldg(&g_edata[i]);
        int2 e1 = __ldg(&g_edata[i + 1]);
        float4 y0 = *(const float4*)&g_Y[(size_t)e0.x * DD + off];
        float4 r0 = *(const float4*)&g_R[e0.y * DD + off];
        float4 y1 = *(const float4*)&g_Y[(size_t)e1.x * DD + off];
        float4 r1 = *(const float4*)&g_R[e1.y * DD + off];
        acc.x += (y0.x - r0.x) + (y1.x - r1.x);
        acc.y += (y0.y - r0.y) + (y1.y - r1.y);
        acc.z += (y0.z - r0.z) + (y1.z - r1.z);
        acc.w += (y0.w - r0.w) + (y1.w - r1.w);
    }
    if (i < end) {
        int2 e0 = __ldg(&g_edata[i]);
        float4 y0 = *(const float4*)&g_Y[(size_t)e0.x * DD + off];
        float4 r0 = *(const float4*)&g_R[e0.y * DD + off];
        acc.x += y0.x - r0.x;
        acc.y += y0.y - r0.y;
        acc.z += y0.z - r0.z;
        acc.w += y0.w - r0.w;
    }
    float* H = TO_OUT ? extout : g_H;
    float4 h = *(float4*)&H[(size_t)node * DD + off];
    h.x += acc.x; h.y += acc.y; h.z += acc.z; h.w += acc.w;
    *(float4*)&H[(size_t)node * DD + off] = h;
}

// ---------------------------------------------------------------------------
extern "C" void kernel_launch(void* const* d_in, const int* in_sizes, int n_in,
                              void* d_out, int out_size) {
    const float* x    = (const float*)d_in[0];
    const int*   ei   = (const int*)d_in[1];
    const int*   et   = (const int*)d_in[2];
    const float* W_I1 = (const float*)d_in[3];
    const float* W_O1 = (const float*)d_in[4];
    const float* rel1 = (const float*)d_in[5];
    const float* b1   = (const float*)d_in[6];
    const float* W_I2 = (const float*)d_in[7];
    const float* W_O2 = (const float*)d_in[8];
    const float* rel2 = (const float*)d_in[9];
    const float* b2   = (const float*)d_in[10];
    float* out = (float*)d_out;

    int M = in_sizes[0] / DD;      // 50000
    int E = in_sizes[2];           // 800000
    const int* src = ei;
    const int* dst = ei + E;

    int gemm_blocks = (M + 127) / 128;
    int gath_blocks = (M + 7) / 8;

    // ---- edge CSR build (shared by both layers) ----
    zero_kernel<<<(M + 255) / 256, 256>>>(M);
    hist_kernel<<<(E + 255) / 256, 256>>>(dst, E);
    scan_kernel<<<1, 1024>>>(M);
    fill_kernel<<<(E + 255) / 256, 256>>>(src, dst, et, E);

    // ---- layer 1 ----
    packw_kernel<<<(DD * 256 + 255) / 256, 256>>>(W_I1, W_O1);
    relgemm_kernel<<<NRELMX, DD>>>(rel1, W_I1);
    gemm_fused_kernel<false, false, false><<<gemm_blocks, 512>>>(x, b1, nullptr, M);
    gather_kernel<false><<<gath_blocks, 256>>>(nullptr, M);

    // ---- layer 2 (ReLU folded into GEMM A-load) ----
    packw_kernel<<<(DD * 256 + 255) / 256, 256>>>(W_I2, W_O2);
    relgemm_kernel<<<NRELMX, DD>>>(rel2, W_I2);
    gemm_fused_kernel<true, true, true><<<gemm_blocks, 512>>>(nullptr, b2, out, M);
    gather_kernel<true><<<gath_blocks, 256>>>(out, M);
}

// round 4
// speedup vs baseline: 1.2186x; 1.0136x over previous
#include <cuda_runtime.h>
#include <cuda_bf16.h>
#include <cstdint>

#define NMAX   50000
#define EMAX   800000
#define DD     128
#define NRELMX 237

// SMEM layout (bytes), A/B bf16 row-major stride 136 elements (=272B, 17*16)
#define SA      136
#define AHI_OFF 0
#define ALO_OFF 34816
#define BHI_OFF 69632
#define BLO_OFF 139264
#define SM_BYTES 208896

// ---------------- static device scratch ------------------------------------
__device__ float g_Y[(size_t)NMAX * DD];      // X@W_I^T (for edge gather)
__device__ float g_H[(size_t)NMAX * DD];      // layer-1 hidden
__device__ float g_R[NRELMX * DD];            // rel @ W_I^T
__device__ int   g_cnt[NMAX];
__device__ int   g_fill[NMAX];
__device__ int   g_rowstart[NMAX + 1];
__device__ int2  g_edata[EMAX];
// Pre-packed B images [256][136] bf16 (interleaved Y/Z cols), hi/lo
__device__ uint4 g_Bhi[(256 * SA * 2) / 16];
__device__ uint4 g_Blo[(256 * SA * 2) / 16];

// ---------------- PTX helpers ------------------------------------------------
__device__ __forceinline__ uint32_t smem_to_u32(const void* p) {
    uint32_t a;
    asm("{ .reg .u64 t; cvta.to.shared.u64 t, %1; cvt.u32.u64 %0, t; }" : "=r"(a) : "l"(p));
    return a;
}
__device__ __forceinline__ void ldmx4(uint32_t* r, uint32_t addr) {
    asm volatile("ldmatrix.sync.aligned.m8n8.x4.shared.b16 {%0,%1,%2,%3}, [%4];"
                 : "=r"(r[0]), "=r"(r[1]), "=r"(r[2]), "=r"(r[3]) : "r"(addr));
}
__device__ __forceinline__ void mma16816(float* d, const uint32_t* a, const uint32_t* b) {
    asm volatile(
        "mma.sync.aligned.m16n8k16.row.col.f32.bf16.bf16.f32 "
        "{%0,%1,%2,%3}, {%4,%5,%6,%7}, {%8,%9}, {%0,%1,%2,%3};"
        : "+f"(d[0]), "+f"(d[1]), "+f"(d[2]), "+f"(d[3])
        : "r"(a[0]), "r"(a[1]), "r"(a[2]), "r"(a[3]), "r"(b[0]), "r"(b[1]));
}
__device__ __forceinline__ uint32_t pack_bf2(__nv_bfloat16 a, __nv_bfloat16 b) {
    __nv_bfloat162 t(a, b);
    return *reinterpret_cast<uint32_t*>(&t);
}

// ---------------- B pack: [256][136] bf16 hi/lo, cols interleaved Y/Z -------
// row r: r=2c -> W_I[c][k] (Y), r=2c+1 -> W_O[c][k] (Z)
__global__ void packb_kernel(const float* __restrict__ W_I,
                             const float* __restrict__ W_O) {
    int idx = blockIdx.x * blockDim.x + threadIdx.x;  // 0..32767
    if (idx >= 256 * DD) return;
    int r = idx >> 7;
    int k = idx & 127;
    int c = r >> 1;
    float v = (r & 1) ? W_O[c * DD + k] : W_I[c * DD + k];
    __nv_bfloat16 hi = __float2bfloat16(v);
    __nv_bfloat16 lo = __float2bfloat16(v - __bfloat162float(hi));
    uint32_t off = (uint32_t)(r * SA + k) * 2u;
    *(__nv_bfloat16*)((char*)g_Bhi + off) = hi;
    *(__nv_bfloat16*)((char*)g_Blo + off) = lo;
}

// ---------------- R[r][n] = sum_k rel[r][k] * W_I[n][k] (exact fp32) --------
__global__ void relgemm_kernel(const float* __restrict__ rel,
                               const float* __restrict__ W_I) {
    __shared__ float rr[DD];
    int r = blockIdx.x;
    int n = threadIdx.x;
    rr[n] = rel[r * DD + n];
    __syncthreads();
    const float4* w4 = (const float4*)(W_I + n * DD);
    float s = 0.f;
#pragma unroll
    for (int kk = 0; kk < DD / 4; kk++) {
        float4 wv = w4[kk];
        s += rr[4 * kk + 0] * wv.x + rr[4 * kk + 1] * wv.y +
             rr[4 * kk + 2] * wv.z + rr[4 * kk + 3] * wv.w;
    }
    g_R[r * DD + n] = s;
}

// ---------------- edge CSR build --------------------------------------------
__global__ void zero_kernel(int M) {
    int i = blockIdx.x * blockDim.x + threadIdx.x;
    if (i < M) { g_cnt[i] = 0; g_fill[i] = 0; }
}
__global__ void hist_kernel(const int* __restrict__ dst, int E) {
    int e = blockIdx.x * blockDim.x + threadIdx.x;
    if (e < E) atomicAdd(&g_cnt[dst[e]], 1);
}
__global__ __launch_bounds__(1024) void scan_kernel(int M) {
    __shared__ int ssum[1024];
    int t = threadIdx.x;
    const int CH = (M + 1023) / 1024;
    int beg = t * CH;
    int s = 0;
    for (int i = 0; i < CH; i++) {
        int idx = beg + i;
        if (idx < M) s += g_cnt[idx];
    }
    ssum[t] = s;
    __syncthreads();
    for (int off = 1; off < 1024; off <<= 1) {
        int v = (t >= off) ? ssum[t - off] : 0;
        __syncthreads();
        ssum[t] += v;
        __syncthreads();
    }
    int pre = (t == 0) ? 0 : ssum[t - 1];
    for (int i = 0; i < CH; i++) {
        int idx = beg + i;
        if (idx < M) {
            g_rowstart[idx] = pre;
            pre += g_cnt[idx];
        }
    }
    if (t == 1023) g_rowstart[M] = pre;
}
__global__ void fill_kernel(const int* __restrict__ src,
                            const int* __restrict__ dst,
                            const int* __restrict__ et, int E) {
    int e = blockIdx.x * blockDim.x + threadIdx.x;
    if (e >= E) return;
    int d = dst[e];
    int pos = g_rowstart[d] + atomicAdd(&g_fill[d], 1);
    g_edata[pos] = make_int2(src[e], et[e]);
}

// ---------------- HMMA GEMM: [Y|Z interleaved] = A @ B^T, fused epilogue ----
// D = Ahi*Bhi + Ahi*Blo + Alo*Bhi (3-term bf16 split, fp32 reg accum)
// 512 threads, 16 warps: warp (wm=wid&3, wn=wid>>2) -> rows wm*32+..., cols wn*64 (n')
template <bool RELU, bool FROM_H, bool TO_OUT>
__global__ __launch_bounds__(512, 1)
void gemm_mma_kernel(const float* __restrict__ Ain,
                     const float* __restrict__ bias,
                     float* __restrict__ extout, int M) {
    extern __shared__ char smem[];
    uint32_t sb = smem_to_u32(smem);
    int tid = threadIdx.x;
    int wid = tid >> 5;
    int lane = tid & 31;
    const float* A = FROM_H ? g_H : Ain;

    // ---- B copy: two 69632B images = 4352 uint4 each ----
    {
        uint4* bh = (uint4*)(smem + BHI_OFF);
        uint4* bl = (uint4*)(smem + BLO_OFF);
#pragma unroll
        for (int i = 0; i < 9; i++) {
            int idx = tid + i * 512;
            if (idx < 4352) { bh[idx] = g_Bhi[idx]; bl[idx] = g_Blo[idx]; }
        }
    }

    // ---- A convert: row = tid/4, cols (tid&3)*32 .. +31 ----
    {
        int row = tid >> 2;
        int c0 = (tid & 3) * 32;
        int gm = blockIdx.x * 128 + row;
#pragma unroll
        for (int f = 0; f < 8; f++) {
            int c = c0 + f * 4;
            float4 v = make_float4(0.f, 0.f, 0.f, 0.f);
            if (gm < M) v = *(const float4*)(A + (size_t)gm * DD + c);
            if (RELU) {
                v.x = fmaxf(v.x, 0.f); v.y = fmaxf(v.y, 0.f);
                v.z = fmaxf(v.z, 0.f); v.w = fmaxf(v.w, 0.f);
            }
            __nv_bfloat16 hx = __float2bfloat16(v.x);
            __nv_bfloat16 hy = __float2bfloat16(v.y);
            __nv_bfloat16 hz = __float2bfloat16(v.z);
            __nv_bfloat16 hw = __float2bfloat16(v.w);
            __nv_bfloat16 lx = __float2bfloat16(v.x - __bfloat162float(hx));
            __nv_bfloat16 ly = __float2bfloat16(v.y - __bfloat162float(hy));
            __nv_bfloat16 lz = __float2bfloat16(v.z - __bfloat162float(hz));
            __nv_bfloat16 lw = __float2bfloat16(v.w - __bfloat162float(hw));
            uint32_t off = (uint32_t)(row * SA + c) * 2u;
            *(uint2*)(smem + AHI_OFF + off) = make_uint2(pack_bf2(hx, hy), pack_bf2(hz, hw));
            *(uint2*)(smem + ALO_OFF + off) = make_uint2(pack_bf2(lx, ly), pack_bf2(lz, lw));
        }
    }
    __syncthreads();

    int wm = wid & 3;       // row group: rows wm*32 .. +31
    int wn = wid >> 2;      // col group: n' cols wn*64 .. +63
    int grp = lane >> 3;
    int r8 = lane & 7;

    float acc[2][8][4];
#pragma unroll
    for (int mt = 0; mt < 2; mt++)
#pragma unroll
        for (int nt = 0; nt < 8; nt++)
#pragma unroll
            for (int q = 0; q < 4; q++) acc[mt][nt][q] = 0.f;

#pragma unroll
    for (int term = 0; term < 3; term++) {
        uint32_t Ab = sb + ((term < 2) ? AHI_OFF : ALO_OFF);
        uint32_t Bb = sb + ((term == 1) ? BLO_OFF : BHI_OFF);
#pragma unroll
        for (int ks = 0; ks < 8; ks++) {
            int k0 = ks * 16;
            uint32_t afrag[2][4];
#pragma unroll
            for (int mt = 0; mt < 2; mt++) {
                int arow = wm * 32 + mt * 16 + (grp & 1) * 8 + r8;
                int acol = k0 + (grp >> 1) * 8;
                ldmx4(afrag[mt], Ab + (uint32_t)(arow * SA + acol) * 2u);
            }
            uint32_t bfrag[8][2];
#pragma unroll
            for (int np = 0; np < 4; np++) {
                int brow = wn * 64 + np * 16 + (grp >> 1) * 8 + r8;
                int bcol = k0 + (grp & 1) * 8;
                uint32_t t[4];
                ldmx4(t, Bb + (uint32_t)(brow * SA + bcol) * 2u);
                bfrag[np * 2][0] = t[0]; bfrag[np * 2][1] = t[1];
                bfrag[np * 2 + 1][0] = t[2]; bfrag[np * 2 + 1][1] = t[3];
            }
#pragma unroll
            for (int mt = 0; mt < 2; mt++)
#pragma unroll
                for (int nt = 0; nt < 8; nt++)
                    mma16816(acc[mt][nt], afrag[mt], bfrag[nt]);
        }
    }
    __syncthreads();   // done with A/B smem; reuse for staging

    // ---- stage epilogue into smem: Ys[128][132], Hs[128][132] fp32 ----
    float* Ys = (float*)smem;
    float* Hs = (float*)(smem + 67584);
#pragma unroll
    for (int nt = 0; nt < 8; nt++) {
        int c = wn * 32 + nt * 4 + (lane & 3);
        float rb = bias[c] - g_R[c];
#pragma unroll
        for (int mt = 0; mt < 2; mt++) {
            int row0 = wm * 32 + mt * 16 + (lane >> 2);
            float y0 = acc[mt][nt][0], z0 = acc[mt][nt][1];
            float y1 = acc[mt][nt][2], z1 = acc[mt][nt][3];
            Ys[row0 * 132 + c] = y0;
            Hs[row0 * 132 + c] = y0 + z0 + rb;
            Ys[(row0 + 8) * 132 + c] = y1;
            Hs[(row0 + 8) * 132 + c] = y1 + z1 + rb;
        }
    }
    __syncthreads();

    // ---- coalesced copy-out: 128 rows x 32 float4 per array ----
    float* H = TO_OUT ? extout : g_H;
#pragma unroll
    for (int i = 0; i < 8; i++) {
        int slot = tid + i * 512;
        int row = slot >> 5;
        int c4 = (slot & 31) * 4;
        int gm = blockIdx.x * 128 + row;
        if (gm < M) {
            float4 yv = *(const float4*)&Ys[row * 132 + c4];
            float4 hv = *(const float4*)&Hs[row * 132 + c4];
            *(float4*)&g_Y[(size_t)gm * DD + c4] = yv;
            *(float4*)&H[(size_t)gm * DD + c4] = hv;
        }
    }
}

// ---------------- gather: H[n] += sum over in-edges of (Y[src] - R[et]) -----
template <bool TO_OUT>
__global__ __launch_bounds__(256) void gather_kernel(float* __restrict__ extout, int M) {
    int node = blockIdx.x * 8 + (threadIdx.x >> 5);
    if (node >= M) return;
    int lane = threadIdx.x & 31;
    int off = lane * 4;
    int beg = g_rowstart[node];
    int end = g_rowstart[node + 1];
    float4 acc = make_float4(0.f, 0.f, 0.f, 0.f);
    int i = beg;
    for (; i + 1 < end; i += 2) {
        int2 e0 = __ldg(&g_edata[i]);
        int2 e1 = __ldg(&g_edata[i + 1]);
        float4 y0 = *(const float4*)&g_Y[(size_t)e0.x * DD + off];
        float4 r0 = *(const float4*)&g_R[e0.y * DD + off];
        float4 y1 = *(const float4*)&g_Y[(size_t)e1.x * DD + off];
        float4 r1 = *(const float4*)&g_R[e1.y * DD + off];
        acc.x += (y0.x - r0.x) + (y1.x - r1.x);
        acc.y += (y0.y - r0.y) + (y1.y - r1.y);
        acc.z += (y0.z - r0.z) + (y1.z - r1.z);
        acc.w += (y0.w - r0.w) + (y1.w - r1.w);
    }
    if (i < end) {
        int2 e0 = __ldg(&g_edata[i]);
        float4 y0 = *(const float4*)&g_Y[(size_t)e0.x * DD + off];
        float4 r0 = *(const float4*)&g_R[e0.y * DD + off];
        acc.x += y0.x - r0.x;
        acc.y += y0.y - r0.y;
        acc.z += y0.z - r0.z;
        acc.w += y0.w - r0.w;
    }
    float* H = TO_OUT ? extout : g_H;
    float4 h = *(float4*)&H[(size_t)node * DD + off];
    h.x += acc.x; h.y += acc.y; h.z += acc.z; h.w += acc.w;
    *(float4*)&H[(size_t)node * DD + off] = h;
}

// ---------------------------------------------------------------------------
extern "C" void kernel_launch(void* const* d_in, const int* in_sizes, int n_in,
                              void* d_out, int out_size) {
    const float* x    = (const float*)d_in[0];
    const int*   ei   = (const int*)d_in[1];
    const int*   et   = (const int*)d_in[2];
    const float* W_I1 = (const float*)d_in[3];
    const float* W_O1 = (const float*)d_in[4];
    const float* rel1 = (const float*)d_in[5];
    const float* b1   = (const float*)d_in[6];
    const float* W_I2 = (const float*)d_in[7];
    const float* W_O2 = (const float*)d_in[8];
    const float* rel2 = (const float*)d_in[9];
    const float* b2   = (const float*)d_in[10];
    float* out = (float*)d_out;

    int M = in_sizes[0] / DD;      // 50000
    int E = in_sizes[2];           // 800000
    const int* src = ei;
    const int* dst = ei + E;

    cudaFuncSetAttribute(gemm_mma_kernel<false, false, false>,
                         cudaFuncAttributeMaxDynamicSharedMemorySize, SM_BYTES);
    cudaFuncSetAttribute(gemm_mma_kernel<true, true, true>,
                         cudaFuncAttributeMaxDynamicSharedMemorySize, SM_BYTES);

    int gemm_blocks = (M + 127) / 128;
    int gath_blocks = (M + 7) / 8;

    // ---- edge CSR build (shared by both layers) ----
    zero_kernel<<<(M + 255) / 256, 256>>>(M);
    hist_kernel<<<(E + 255) / 256, 256>>>(dst, E);
    scan_kernel<<<1, 1024>>>(M);
    fill_kernel<<<(E + 255) / 256, 256>>>(src, dst, et, E);

    // ---- layer 1 ----
    packb_kernel<<<(256 * DD + 255) / 256, 256>>>(W_I1, W_O1);
    relgemm_kernel<<<NRELMX, DD>>>(rel1, W_I1);
    gemm_mma_kernel<false, false, false><<<gemm_blocks, 512, SM_BYTES>>>(x, b1, nullptr, M);
    gather_kernel<false><<<gath_blocks, 256>>>(nullptr, M);

    // ---- layer 2 (ReLU folded into A conversion) ----
    packb_kernel<<<(256 * DD + 255) / 256, 256>>>(W_I2, W_O2);
    relgemm_kernel<<<NRELMX, DD>>>(rel2, W_I2);
    gemm_mma_kernel<true, true, true><<<gemm_blocks, 512, SM_BYTES>>>(nullptr, b2, out, M);
    gather_kernel<true><<<gath_blocks, 256>>>(out, M);
}

// round 6
// speedup vs baseline: 1.4018x; 1.1503x over previous
#include <cuda_runtime.h>
#include <cuda_bf16.h>
#include <cstdint>

#define NMAX   50000
#define EMAX   800000
#define DD     128
#define NRELMX 237

// SMEM layout (bytes): A/B bf16 row-major stride 136 elems (=272B)
#define SA      136
#define AHI_OFF 0
#define ALO_OFF 17408
#define BHI_OFF 34816
#define BLO_OFF 69632
#define SM_BYTES 104448
// staging (reuses A region): Ys[64][68], Hs[64][68] fp32 (272B row = 17*16, aligned)
#define YS_OFF  0
#define HS_OFF  17408

// ---------------- static device scratch ------------------------------------
__device__ float g_Y[(size_t)NMAX * DD];      // X@W_I^T (for edge gather)
__device__ float g_H[(size_t)NMAX * DD];      // layer-1 hidden
__device__ float g_R[NRELMX * DD];            // rel @ W_I^T
__device__ int   g_cnt[NMAX];
__device__ int   g_rowstart[NMAX + 1];
__device__ int2  g_edata[EMAX];
// Pre-packed B images [256][136] bf16 (interleaved Y/Z cols), hi/lo
__device__ uint4 g_Bhi[(256 * SA * 2) / 16];
__device__ uint4 g_Blo[(256 * SA * 2) / 16];

// ---------------- PTX helpers ------------------------------------------------
__device__ __forceinline__ uint32_t smem_to_u32(const void* p) {
    uint32_t a;
    asm("{ .reg .u64 t; cvta.to.shared.u64 t, %1; cvt.u32.u64 %0, t; }" : "=r"(a) : "l"(p));
    return a;
}
__device__ __forceinline__ void ldmx4(uint32_t* r, uint32_t addr) {
    asm volatile("ldmatrix.sync.aligned.m8n8.x4.shared.b16 {%0,%1,%2,%3}, [%4];"
                 : "=r"(r[0]), "=r"(r[1]), "=r"(r[2]), "=r"(r[3]) : "r"(addr));
}
__device__ __forceinline__ void mma16816(float* d, const uint32_t* a, const uint32_t* b) {
    asm volatile(
        "mma.sync.aligned.m16n8k16.row.col.f32.bf16.bf16.f32 "
        "{%0,%1,%2,%3}, {%4,%5,%6,%7}, {%8,%9}, {%0,%1,%2,%3};"
        : "+f"(d[0]), "+f"(d[1]), "+f"(d[2]), "+f"(d[3])
        : "r"(a[0]), "r"(a[1]), "r"(a[2]), "r"(a[3]), "r"(b[0]), "r"(b[1]));
}
__device__ __forceinline__ uint32_t pack_bf2(__nv_bfloat16 a, __nv_bfloat16 b) {
    __nv_bfloat162 t(a, b);
    return *reinterpret_cast<uint32_t*>(&t);
}

// ---------------- B pack: [256][136] bf16 hi/lo, cols interleaved Y/Z -------
__global__ void packb_kernel(const float* __restrict__ W_I,
                             const float* __restrict__ W_O) {
    int idx = blockIdx.x * blockDim.x + threadIdx.x;  // 0..32767
    if (idx >= 256 * DD) return;
    int r = idx >> 7;
    int k = idx & 127;
    int c = r >> 1;
    float v = (r & 1) ? W_O[c * DD + k] : W_I[c * DD + k];
    __nv_bfloat16 hi = __float2bfloat16(v);
    __nv_bfloat16 lo = __float2bfloat16(v - __bfloat162float(hi));
    uint32_t off = (uint32_t)(r * SA + k) * 2u;
    *(__nv_bfloat16*)((char*)g_Bhi + off) = hi;
    *(__nv_bfloat16*)((char*)g_Blo + off) = lo;
}

// ---------------- R[r][n] = sum_k rel[r][k] * W_I[n][k] (exact fp32) --------
__global__ void relgemm_kernel(const float* __restrict__ rel,
                               const float* __restrict__ W_I) {
    __shared__ float rr[DD];
    int r = blockIdx.x;
    int n = threadIdx.x;
    rr[n] = rel[r * DD + n];
    __syncthreads();
    const float4* w4 = (const float4*)(W_I + n * DD);
    float s = 0.f;
#pragma unroll
    for (int kk = 0; kk < DD / 4; kk++) {
        float4 wv = w4[kk];
        s += rr[4 * kk + 0] * wv.x + rr[4 * kk + 1] * wv.y +
             rr[4 * kk + 2] * wv.z + rr[4 * kk + 3] * wv.w;
    }
    g_R[r * DD + n] = s;
}

// ---------------- edge CSR build --------------------------------------------
__global__ void zero_kernel(int M) {
    int i = blockIdx.x * blockDim.x + threadIdx.x;
    if (i < M) g_cnt[i] = 0;
}
__global__ void hist_kernel(const int* __restrict__ dst, int E) {
    int e = blockIdx.x * blockDim.x + threadIdx.x;
    if (e < E) atomicAdd(&g_cnt[dst[e]], 1);
}
__global__ __launch_bounds__(1024) void scan_kernel(int M) {
    __shared__ int ssum[1024];
    int t = threadIdx.x;
    const int CH = (M + 1023) / 1024;
    int beg = t * CH;
    int s = 0;
    for (int i = 0; i < CH; i++) {
        int idx = beg + i;
        if (idx < M) s += g_cnt[idx];
    }
    ssum[t] = s;
    __syncthreads();
    for (int off = 1; off < 1024; off <<= 1) {
        int v = (t >= off) ? ssum[t - off] : 0;
        __syncthreads();
        ssum[t] += v;
        __syncthreads();
    }
    int pre = (t == 0) ? 0 : ssum[t - 1];
    for (int i = 0; i < CH; i++) {
        int idx = beg + i;
        if (idx < M) {
            g_rowstart[idx] = pre;
            pre += g_cnt[idx];
        }
    }
    if (t == 1023) g_rowstart[M] = pre;
}
// fill post-increments g_rowstart[d]; afterwards g_rowstart[d] == row-end(d)
__global__ void fill_kernel(const int* __restrict__ src,
                            const int* __restrict__ dst,
                            const int* __restrict__ et, int E) {
    int e = blockIdx.x * blockDim.x + threadIdx.x;
    if (e >= E) return;
    int d = dst[e];
    int pos = atomicAdd(&g_rowstart[d], 1);
    g_edata[pos] = make_int2(src[e], et[e]);
}

// ---------------- HMMA GEMM: BM=64, BN=128 n' (64 real cols), occ 2 ---------
// D = Ahi*Bhi + Ahi*Blo + Alo*Bhi (3-term bf16 split, fp32 reg accum)
// 256 threads, 8 warps: wm=wid&1 (rows wm*32..), wn=wid>>1 (n' wn*32..)
template <bool RELU, bool FROM_H, bool TO_OUT>
__global__ __launch_bounds__(256, 2)
void gemm_mma_kernel(const float* __restrict__ Ain,
                     const float* __restrict__ bias,
                     float* __restrict__ extout, int M) {
    extern __shared__ char smem[];
    uint32_t sb = smem_to_u32(smem);
    int tid = threadIdx.x;
    int wid = tid >> 5;
    int lane = tid & 31;
    int bm = blockIdx.x * 64;
    int bn = blockIdx.y;           // n-half (0/1): n' cols bn*128..+127
    const float* A = FROM_H ? g_H : Ain;

    // ---- B copy: rows bn*128..+127 of packed images = 2176 uint4 each ----
    {
        const uint4* sbh = g_Bhi + (size_t)bn * 2176;
        const uint4* sbl = g_Blo + (size_t)bn * 2176;
        uint4* bh = (uint4*)(smem + BHI_OFF);
        uint4* bl = (uint4*)(smem + BLO_OFF);
#pragma unroll
        for (int i = 0; i < 9; i++) {
            int idx = tid + i * 256;
            if (idx < 2176) { bh[idx] = sbh[idx]; bl[idx] = sbl[idx]; }
        }
    }

    // ---- A load (coalesced) + bf16 hi/lo convert: 64x128 = 2048 float4 ----
#pragma unroll
    for (int i = 0; i < 8; i++) {
        int slot = tid + i * 256;
        int row = slot >> 5;
        int c4 = (slot & 31) * 4;
        int gm = bm + row;
        float4 v = make_float4(0.f, 0.f, 0.f, 0.f);
        if (gm < M) v = *(const float4*)(A + (size_t)gm * DD + c4);
        if (RELU) {
            v.x = fmaxf(v.x, 0.f); v.y = fmaxf(v.y, 0.f);
            v.z = fmaxf(v.z, 0.f); v.w = fmaxf(v.w, 0.f);
        }
        __nv_bfloat16 hx = __float2bfloat16(v.x);
        __nv_bfloat16 hy = __float2bfloat16(v.y);
        __nv_bfloat16 hz = __float2bfloat16(v.z);
        __nv_bfloat16 hw = __float2bfloat16(v.w);
        __nv_bfloat16 lx = __float2bfloat16(v.x - __bfloat162float(hx));
        __nv_bfloat16 ly = __float2bfloat16(v.y - __bfloat162float(hy));
        __nv_bfloat16 lz = __float2bfloat16(v.z - __bfloat162float(hz));
        __nv_bfloat16 lw = __float2bfloat16(v.w - __bfloat162float(hw));
        uint32_t off = (uint32_t)(row * SA + c4) * 2u;
        *(uint2*)(smem + AHI_OFF + off) = make_uint2(pack_bf2(hx, hy), pack_bf2(hz, hw));
        *(uint2*)(smem + ALO_OFF + off) = make_uint2(pack_bf2(lx, ly), pack_bf2(lz, lw));
    }
    __syncthreads();

    int wm = wid & 1;
    int wn = wid >> 1;
    int grp = lane >> 3;
    int r8 = lane & 7;

    float acc[2][4][4];
#pragma unroll
    for (int mt = 0; mt < 2; mt++)
#pragma unroll
        for (int nt = 0; nt < 4; nt++)
#pragma unroll
            for (int q = 0; q < 4; q++) acc[mt][nt][q] = 0.f;

#pragma unroll
    for (int term = 0; term < 3; term++) {
        uint32_t Ab = sb + ((term < 2) ? AHI_OFF : ALO_OFF);
        uint32_t Bb = sb + ((term == 1) ? BLO_OFF : BHI_OFF);
#pragma unroll
        for (int ks = 0; ks < 8; ks++) {
            int k0 = ks * 16;
            uint32_t afrag[2][4];
#pragma unroll
            for (int mt = 0; mt < 2; mt++) {
                int arow = wm * 32 + mt * 16 + (grp & 1) * 8 + r8;
                int acol = k0 + (grp >> 1) * 8;
                ldmx4(afrag[mt], Ab + (uint32_t)(arow * SA + acol) * 2u);
            }
            uint32_t bfrag[4][2];
#pragma unroll
            for (int np = 0; np < 2; np++) {
                int brow = wn * 32 + np * 16 + (grp >> 1) * 8 + r8;
                int bcol = k0 + (grp & 1) * 8;
                uint32_t t[4];
                ldmx4(t, Bb + (uint32_t)(brow * SA + bcol) * 2u);
                bfrag[np * 2][0] = t[0]; bfrag[np * 2][1] = t[1];
                bfrag[np * 2 + 1][0] = t[2]; bfrag[np * 2 + 1][1] = t[3];
            }
#pragma unroll
            for (int mt = 0; mt < 2; mt++)
#pragma unroll
                for (int nt = 0; nt < 4; nt++)
                    mma16816(acc[mt][nt], afrag[mt], bfrag[nt]);
        }
    }
    __syncthreads();   // done with A smem; reuse for staging

    // ---- stage: Ys[64][68], Hs[64][68] (local cols 0..63 = bn*64..) ----
    float* Ys = (float*)(smem + YS_OFF);
    float* Hs = (float*)(smem + HS_OFF);
#pragma unroll
    for (int nt = 0; nt < 4; nt++) {
        int cl = wn * 16 + nt * 4 + (lane & 3);
        int cg = bn * 64 + cl;
        float rb = bias[cg] - g_R[cg];
#pragma unroll
        for (int mt = 0; mt < 2; mt++) {
            int r0 = wm * 32 + mt * 16 + (lane >> 2);
            float y0 = acc[mt][nt][0], z0 = acc[mt][nt][1];
            float y1 = acc[mt][nt][2], z1 = acc[mt][nt][3];
            Ys[r0 * 68 + cl] = y0;
            Hs[r0 * 68 + cl] = y0 + z0 + rb;
            Ys[(r0 + 8) * 68 + cl] = y1;
            Hs[(r0 + 8) * 68 + cl] = y1 + z1 + rb;
        }
    }
    __syncthreads();

    // ---- coalesced copy-out: 64 rows x 16 float4 per array ----
    float* H = TO_OUT ? extout : g_H;
#pragma unroll
    for (int i = 0; i < 4; i++) {
        int slot = tid + i * 256;
        int row = slot >> 4;
        int c4 = (slot & 15) * 4;
        int gm = bm + row;
        if (gm < M) {
            float4 yv = *(const float4*)&Ys[row * 68 + c4];
            float4 hv = *(const float4*)&Hs[row * 68 + c4];
            *(float4*)&g_Y[(size_t)gm * DD + bn * 64 + c4] = yv;
            *(float4*)&H[(size_t)gm * DD + bn * 64 + c4] = hv;
        }
    }
}

// ---------------- gather: H[n] += sum over in-edges of (Y[src] - R[et]) -----
template <bool TO_OUT>
__global__ __launch_bounds__(256) void gather_kernel(float* __restrict__ extout, int M) {
    int node = blockIdx.x * 8 + (threadIdx.x >> 5);
    if (node >= M) return;
    int lane = threadIdx.x & 31;
    int off = lane * 4;
    int beg = node ? __ldg(&g_rowstart[node - 1]) : 0;
    int end = __ldg(&g_rowstart[node]);
    float4 acc = make_float4(0.f, 0.f, 0.f, 0.f);
    int i = beg;
    for (; i + 1 < end; i += 2) {
        int2 e0 = __ldg(&g_edata[i]);
        int2 e1 = __ldg(&g_edata[i + 1]);
        float4 y0 = *(const float4*)&g_Y[(size_t)e0.x * DD + off];
        float4 r0 = *(const float4*)&g_R[e0.y * DD + off];
        float4 y1 = *(const float4*)&g_Y[(size_t)e1.x * DD + off];
        float4 r1 = *(const float4*)&g_R[e1.y * DD + off];
        acc.x += (y0.x - r0.x) + (y1.x - r1.x);
        acc.y += (y0.y - r0.y) + (y1.y - r1.y);
        acc.z += (y0.z - r0.z) + (y1.z - r1.z);
        acc.w += (y0.w - r0.w) + (y1.w - r1.w);
    }
    if (i < end) {
        int2 e0 = __ldg(&g_edata[i]);
        float4 y0 = *(const float4*)&g_Y[(size_t)e0.x * DD + off];
        float4 r0 = *(const float4*)&g_R[e0.y * DD + off];
        acc.x += y0.x - r0.x;
        acc.y += y0.y - r0.y;
        acc.z += y0.z - r0.z;
        acc.w += y0.w - r0.w;
    }
    float* H = TO_OUT ? extout : g_H;
    float4 h = *(float4*)&H[(size_t)node * DD + off];
    h.x += acc.x; h.y += acc.y; h.z += acc.z; h.w += acc.w;
    *(float4*)&H[(size_t)node * DD + off] = h;
}

// ---------------------------------------------------------------------------
extern "C" void kernel_launch(void* const* d_in, const int* in_sizes, int n_in,
                              void* d_out, int out_size) {
    const float* x    = (const float*)d_in[0];
    const int*   ei   = (const int*)d_in[1];
    const int*   et   = (const int*)d_in[2];
    const float* W_I1 = (const float*)d_in[3];
    const float* W_O1 = (const float*)d_in[4];
    const float* rel1 = (const float*)d_in[5];
    const float* b1   = (const float*)d_in[6];
    const float* W_I2 = (const float*)d_in[7];
    const float* W_O2 = (const float*)d_in[8];
    const float* rel2 = (const float*)d_in[9];
    const float* b2   = (const float*)d_in[10];
    float* out = (float*)d_out;

    int M = in_sizes[0] / DD;      // 50000
    int E = in_sizes[2];           // 800000
    const int* src = ei;
    const int* dst = ei + E;

    cudaFuncSetAttribute(gemm_mma_kernel<false, false, false>,
                         cudaFuncAttributeMaxDynamicSharedMemorySize, SM_BYTES);
    cudaFuncSetAttribute(gemm_mma_kernel<true, true, true>,
                         cudaFuncAttributeMaxDynamicSharedMemorySize, SM_BYTES);

    dim3 ggemm((M + 63) / 64, 2);
    int gath_blocks = (M + 7) / 8;

    // ---- edge CSR build (shared by both layers) ----
    zero_kernel<<<(M + 255) / 256, 256>>>(M);
    hist_kernel<<<(E + 255) / 256, 256>>>(dst, E);
    scan_kernel<<<1, 1024>>>(M);
    fill_kernel<<<(E + 255) / 256, 256>>>(src, dst, et, E);

    // ---- layer 1 ----
    packb_kernel<<<(256 * DD + 255) / 256, 256>>>(W_I1, W_O1);
    relgemm_kernel<<<NRELMX, DD>>>(rel1, W_I1);
    gemm_mma_kernel<false, false, false><<<ggemm, 256, SM_BYTES>>>(x, b1, nullptr, M);
    gather_kernel<false><<<gath_blocks, 256>>>(nullptr, M);

    // ---- layer 2 (ReLU folded into A conversion) ----
    packb_kernel<<<(256 * DD + 255) / 256, 256>>>(W_I2, W_O2);
    relgemm_kernel<<<NRELMX, DD>>>(rel2, W_I2);
    gemm_mma_kernel<true, true, true><<<ggemm, 256, SM_BYTES>>>(nullptr, b2, out, M);
    gather_kernel<true><<<gath_blocks, 256>>>(out, M);
}

// round 7
// speedup vs baseline: 1.4907x; 1.0634x over previous
#include <cuda_runtime.h>
#include <cuda_bf16.h>
#include <cuda_fp16.h>
#include <cstdint>

#define NMAX   50000
#define EMAX   800000
#define DD     128
#define NRELMX 237

// SMEM layout (bytes): A/B bf16 row-major stride 136 elems (=272B)
#define SA      136
#define AHI_OFF 0
#define ALO_OFF 17408
#define BHI_OFF 34816
#define BLO_OFF 69632
#define SM_BYTES 104448
// staging (reuses A region): Ysh[64][72] fp16 (144B row, 16-mult), Hs[64][68] fp32
#define YS_OFF  0
#define HS_OFF  17408

// ---------------- static device scratch ------------------------------------
__device__ __half g_Yh[(size_t)NMAX * DD];    // X@W_I^T in fp16 (edge gather)
__device__ float  g_H[(size_t)NMAX * DD];     // layer-1 hidden
__device__ float  g_R[NRELMX * DD];           // rel @ W_I^T (fp32, epilogue)
__device__ __half g_Rh[NRELMX * DD];          // fp16 copy (edge gather)
__device__ int    g_cnt[NMAX];
__device__ int    g_rowstart[NMAX + 1];
__device__ int2   g_edata[EMAX];
// Pre-packed B images [256][136] bf16 (interleaved Y/Z cols), hi/lo
__device__ uint4 g_Bhi[(256 * SA * 2) / 16];
__device__ uint4 g_Blo[(256 * SA * 2) / 16];

// ---------------- PTX helpers ------------------------------------------------
__device__ __forceinline__ uint32_t smem_to_u32(const void* p) {
    uint32_t a;
    asm("{ .reg .u64 t; cvta.to.shared.u64 t, %1; cvt.u32.u64 %0, t; }" : "=r"(a) : "l"(p));
    return a;
}
__device__ __forceinline__ void ldmx4(uint32_t* r, uint32_t addr) {
    asm volatile("ldmatrix.sync.aligned.m8n8.x4.shared.b16 {%0,%1,%2,%3}, [%4];"
                 : "=r"(r[0]), "=r"(r[1]), "=r"(r[2]), "=r"(r[3]) : "r"(addr));
}
__device__ __forceinline__ void mma16816(float* d, const uint32_t* a, const uint32_t* b) {
    asm volatile(
        "mma.sync.aligned.m16n8k16.row.col.f32.bf16.bf16.f32 "
        "{%0,%1,%2,%3}, {%4,%5,%6,%7}, {%8,%9}, {%0,%1,%2,%3};"
        : "+f"(d[0]), "+f"(d[1]), "+f"(d[2]), "+f"(d[3])
        : "r"(a[0]), "r"(a[1]), "r"(a[2]), "r"(a[3]), "r"(b[0]), "r"(b[1]));
}
__device__ __forceinline__ uint32_t pack_bf2(__nv_bfloat16 a, __nv_bfloat16 b) {
    __nv_bfloat162 t(a, b);
    return *reinterpret_cast<uint32_t*>(&t);
}

// ---------------- B pack: [256][136] bf16 hi/lo, cols interleaved Y/Z -------
__global__ void packb_kernel(const float* __restrict__ W_I,
                             const float* __restrict__ W_O) {
    int idx = blockIdx.x * blockDim.x + threadIdx.x;  // 0..32767
    if (idx >= 256 * DD) return;
    int r = idx >> 7;
    int k = idx & 127;
    int c = r >> 1;
    float v = (r & 1) ? W_O[c * DD + k] : W_I[c * DD + k];
    __nv_bfloat16 hi = __float2bfloat16(v);
    __nv_bfloat16 lo = __float2bfloat16(v - __bfloat162float(hi));
    uint32_t off = (uint32_t)(r * SA + k) * 2u;
    *(__nv_bfloat16*)((char*)g_Bhi + off) = hi;
    *(__nv_bfloat16*)((char*)g_Blo + off) = lo;
}

// ---------------- R[r][n] = sum_k rel[r][k] * W_I[n][k] (exact fp32) --------
__global__ void relgemm_kernel(const float* __restrict__ rel,
                               const float* __restrict__ W_I) {
    __shared__ float rr[DD];
    int r = blockIdx.x;
    int n = threadIdx.x;
    rr[n] = rel[r * DD + n];
    __syncthreads();
    const float4* w4 = (const float4*)(W_I + n * DD);
    float s = 0.f;
#pragma unroll
    for (int kk = 0; kk < DD / 4; kk++) {
        float4 wv = w4[kk];
        s += rr[4 * kk + 0] * wv.x + rr[4 * kk + 1] * wv.y +
             rr[4 * kk + 2] * wv.z + rr[4 * kk + 3] * wv.w;
    }
    g_R[r * DD + n] = s;
    g_Rh[r * DD + n] = __float2half(s);
}

// ---------------- edge CSR build --------------------------------------------
__global__ void zero_kernel(int M) {
    int i = blockIdx.x * blockDim.x + threadIdx.x;
    if (i < M) g_cnt[i] = 0;
}
__global__ void hist_kernel(const int* __restrict__ dst, int E) {
    int e = blockIdx.x * blockDim.x + threadIdx.x;
    if (e < E) atomicAdd(&g_cnt[dst[e]], 1);
}
__global__ __launch_bounds__(1024) void scan_kernel(int M) {
    __shared__ int ssum[1024];
    int t = threadIdx.x;
    const int CH = (M + 1023) / 1024;
    int beg = t * CH;
    int s = 0;
    for (int i = 0; i < CH; i++) {
        int idx = beg + i;
        if (idx < M) s += g_cnt[idx];
    }
    ssum[t] = s;
    __syncthreads();
    for (int off = 1; off < 1024; off <<= 1) {
        int v = (t >= off) ? ssum[t - off] : 0;
        __syncthreads();
        ssum[t] += v;
        __syncthreads();
    }
    int pre = (t == 0) ? 0 : ssum[t - 1];
    for (int i = 0; i < CH; i++) {
        int idx = beg + i;
        if (idx < M) {
            g_rowstart[idx] = pre;
            pre += g_cnt[idx];
        }
    }
    if (t == 1023) g_rowstart[M] = pre;
}
// fill post-increments g_rowstart[d]; afterwards g_rowstart[d] == row-end(d)
__global__ void fill_kernel(const int* __restrict__ src,
                            const int* __restrict__ dst,
                            const int* __restrict__ et, int E) {
    int e = blockIdx.x * blockDim.x + threadIdx.x;
    if (e >= E) return;
    int d = dst[e];
    int pos = atomicAdd(&g_rowstart[d], 1);
    g_edata[pos] = make_int2(src[e], et[e]);
}

// ---------------- HMMA GEMM: BM=64, BN=128 n' (64 real cols), occ 2 ---------
// D = Ahi*Bhi + Ahi*Blo + Alo*Bhi (3-term bf16 split, fp32 reg accum)
template <bool RELU, bool FROM_H, bool TO_OUT>
__global__ __launch_bounds__(256, 2)
void gemm_mma_kernel(const float* __restrict__ Ain,
                     const float* __restrict__ bias,
                     float* __restrict__ extout, int M) {
    extern __shared__ char smem[];
    uint32_t sb = smem_to_u32(smem);
    int tid = threadIdx.x;
    int wid = tid >> 5;
    int lane = tid & 31;
    int bm = blockIdx.x * 64;
    int bn = blockIdx.y;           // n-half (0/1)
    const float* A = FROM_H ? g_H : Ain;

    // ---- B copy: rows bn*128..+127 of packed images = 2176 uint4 each ----
    {
        const uint4* sbh = g_Bhi + (size_t)bn * 2176;
        const uint4* sbl = g_Blo + (size_t)bn * 2176;
        uint4* bh = (uint4*)(smem + BHI_OFF);
        uint4* bl = (uint4*)(smem + BLO_OFF);
#pragma unroll
        for (int i = 0; i < 9; i++) {
            int idx = tid + i * 256;
            if (idx < 2176) { bh[idx] = sbh[idx]; bl[idx] = sbl[idx]; }
        }
    }

    // ---- A load (coalesced) + bf16 hi/lo convert: 64x128 = 2048 float4 ----
#pragma unroll
    for (int i = 0; i < 8; i++) {
        int slot = tid + i * 256;
        int row = slot >> 5;
        int c4 = (slot & 31) * 4;
        int gm = bm + row;
        float4 v = make_float4(0.f, 0.f, 0.f, 0.f);
        if (gm < M) v = *(const float4*)(A + (size_t)gm * DD + c4);
        if (RELU) {
            v.x = fmaxf(v.x, 0.f); v.y = fmaxf(v.y, 0.f);
            v.z = fmaxf(v.z, 0.f); v.w = fmaxf(v.w, 0.f);
        }
        __nv_bfloat16 hx = __float2bfloat16(v.x);
        __nv_bfloat16 hy = __float2bfloat16(v.y);
        __nv_bfloat16 hz = __float2bfloat16(v.z);
        __nv_bfloat16 hw = __float2bfloat16(v.w);
        __nv_bfloat16 lx = __float2bfloat16(v.x - __bfloat162float(hx));
        __nv_bfloat16 ly = __float2bfloat16(v.y - __bfloat162float(hy));
        __nv_bfloat16 lz = __float2bfloat16(v.z - __bfloat162float(hz));
        __nv_bfloat16 lw = __float2bfloat16(v.w - __bfloat162float(hw));
        uint32_t off = (uint32_t)(row * SA + c4) * 2u;
        *(uint2*)(smem + AHI_OFF + off) = make_uint2(pack_bf2(hx, hy), pack_bf2(hz, hw));
        *(uint2*)(smem + ALO_OFF + off) = make_uint2(pack_bf2(lx, ly), pack_bf2(lz, lw));
    }
    __syncthreads();

    int wm = wid & 1;
    int wn = wid >> 1;
    int grp = lane >> 3;
    int r8 = lane & 7;

    float acc[2][4][4];
#pragma unroll
    for (int mt = 0; mt < 2; mt++)
#pragma unroll
        for (int nt = 0; nt < 4; nt++)
#pragma unroll
            for (int q = 0; q < 4; q++) acc[mt][nt][q] = 0.f;

#pragma unroll
    for (int term = 0; term < 3; term++) {
        uint32_t Ab = sb + ((term < 2) ? AHI_OFF : ALO_OFF);
        uint32_t Bb = sb + ((term == 1) ? BLO_OFF : BHI_OFF);
#pragma unroll
        for (int ks = 0; ks < 8; ks++) {
            int k0 = ks * 16;
            uint32_t afrag[2][4];
#pragma unroll
            for (int mt = 0; mt < 2; mt++) {
                int arow = wm * 32 + mt * 16 + (grp & 1) * 8 + r8;
                int acol = k0 + (grp >> 1) * 8;
                ldmx4(afrag[mt], Ab + (uint32_t)(arow * SA + acol) * 2u);
            }
            uint32_t bfrag[4][2];
#pragma unroll
            for (int np = 0; np < 2; np++) {
                int brow = wn * 32 + np * 16 + (grp >> 1) * 8 + r8;
                int bcol = k0 + (grp & 1) * 8;
                uint32_t t[4];
                ldmx4(t, Bb + (uint32_t)(brow * SA + bcol) * 2u);
                bfrag[np * 2][0] = t[0]; bfrag[np * 2][1] = t[1];
                bfrag[np * 2 + 1][0] = t[2]; bfrag[np * 2 + 1][1] = t[3];
            }
#pragma unroll
            for (int mt = 0; mt < 2; mt++)
#pragma unroll
                for (int nt = 0; nt < 4; nt++)
                    mma16816(acc[mt][nt], afrag[mt], bfrag[nt]);
        }
    }
    __syncthreads();   // done with A smem; reuse for staging

    // ---- stage: Ysh[64][72] fp16, Hs[64][68] fp32 ----
    __half* Ysh = (__half*)(smem + YS_OFF);
    float* Hs = (float*)(smem + HS_OFF);
#pragma unroll
    for (int nt = 0; nt < 4; nt++) {
        int cl = wn * 16 + nt * 4 + (lane & 3);
        int cg = bn * 64 + cl;
        float rb = bias[cg] - g_R[cg];
#pragma unroll
        for (int mt = 0; mt < 2; mt++) {
            int r0 = wm * 32 + mt * 16 + (lane >> 2);
            float y0 = acc[mt][nt][0], z0 = acc[mt][nt][1];
            float y1 = acc[mt][nt][2], z1 = acc[mt][nt][3];
            Ysh[r0 * 72 + cl] = __float2half(y0);
            Hs[r0 * 68 + cl] = y0 + z0 + rb;
            Ysh[(r0 + 8) * 72 + cl] = __float2half(y1);
            Hs[(r0 + 8) * 68 + cl] = y1 + z1 + rb;
        }
    }
    __syncthreads();

    // ---- coalesced copy-out ----
    float* H = TO_OUT ? extout : g_H;
    // H: 64 rows x 16 float4
#pragma unroll
    for (int i = 0; i < 4; i++) {
        int slot = tid + i * 256;
        int row = slot >> 4;
        int c4 = (slot & 15) * 4;
        int gm = bm + row;
        if (gm < M)
            *(float4*)&H[(size_t)gm * DD + bn * 64 + c4] = *(const float4*)&Hs[row * 68 + c4];
    }
    // Y fp16: 64 rows x 16 uint2 (4 halves each)
#pragma unroll
    for (int i = 0; i < 4; i++) {
        int slot = tid + i * 256;
        int row = slot >> 4;
        int c4 = (slot & 15) * 4;
        int gm = bm + row;
        if (gm < M)
            *(uint2*)&g_Yh[(size_t)gm * DD + bn * 64 + c4] = *(const uint2*)&Ysh[row * 72 + c4];
    }
}

// ---------------- gather: H[n] += sum over in-edges of (Yh[src] - Rh[et]) ---
template <bool TO_OUT>
__global__ __launch_bounds__(256) void gather_kernel(float* __restrict__ extout, int M) {
    int node = blockIdx.x * 8 + (threadIdx.x >> 5);
    if (node >= M) return;
    int lane = threadIdx.x & 31;
    int beg = node ? __ldg(&g_rowstart[node - 1]) : 0;
    int end = __ldg(&g_rowstart[node]);
    const uint2* Yh = (const uint2*)g_Yh;   // 32 uint2 per row
    const uint2* Rh = (const uint2*)g_Rh;
    float4 acc = make_float4(0.f, 0.f, 0.f, 0.f);
    int i = beg;
    for (; i + 1 < end; i += 2) {
        int2 e0 = __ldg(&g_edata[i]);
        int2 e1 = __ldg(&g_edata[i + 1]);
        uint2 y0 = __ldg(&Yh[(size_t)e0.x * 32 + lane]);
        uint2 r0 = __ldg(&Rh[(size_t)e0.y * 32 + lane]);
        uint2 y1 = __ldg(&Yh[(size_t)e1.x * 32 + lane]);
        uint2 r1 = __ldg(&Rh[(size_t)e1.y * 32 + lane]);
        float2 ya = __half22float2(*(__half2*)&y0.x), yb = __half22float2(*(__half2*)&y0.y);
        float2 ra = __half22float2(*(__half2*)&r0.x), rb = __half22float2(*(__half2*)&r0.y);
        float2 yc = __half22float2(*(__half2*)&y1.x), yd = __half22float2(*(__half2*)&y1.y);
        float2 rc = __half22float2(*(__half2*)&r1.x), rd = __half22float2(*(__half2*)&r1.y);
        acc.x += (ya.x - ra.x) + (yc.x - rc.x);
        acc.y += (ya.y - ra.y) + (yc.y - rc.y);
        acc.z += (yb.x - rb.x) + (yd.x - rd.x);
        acc.w += (yb.y - rb.y) + (yd.y - rd.y);
    }
    if (i < end) {
        int2 e0 = __ldg(&g_edata[i]);
        uint2 y0 = __ldg(&Yh[(size_t)e0.x * 32 + lane]);
        uint2 r0 = __ldg(&Rh[(size_t)e0.y * 32 + lane]);
        float2 ya = __half22float2(*(__half2*)&y0.x), yb = __half22float2(*(__half2*)&y0.y);
        float2 ra = __half22float2(*(__half2*)&r0.x), rb = __half22float2(*(__half2*)&r0.y);
        acc.x += ya.x - ra.x;
        acc.y += ya.y - ra.y;
        acc.z += yb.x - rb.x;
        acc.w += yb.y - rb.y;
    }
    float* H = TO_OUT ? extout : g_H;
    int off = lane * 4;
    float4 h = *(float4*)&H[(size_t)node * DD + off];
    h.x += acc.x; h.y += acc.y; h.z += acc.z; h.w += acc.w;
    *(float4*)&H[(size_t)node * DD + off] = h;
}

// ---------------------------------------------------------------------------
extern "C" void kernel_launch(void* const* d_in, const int* in_sizes, int n_in,
                              void* d_out, int out_size) {
    const float* x    = (const float*)d_in[0];
    const int*   ei   = (const int*)d_in[1];
    const int*   et   = (const int*)d_in[2];
    const float* W_I1 = (const float*)d_in[3];
    const float* W_O1 = (const float*)d_in[4];
    const float* rel1 = (const float*)d_in[5];
    const float* b1   = (const float*)d_in[6];
    const float* W_I2 = (const float*)d_in[7];
    const float* W_O2 = (const float*)d_in[8];
    const float* rel2 = (const float*)d_in[9];
    const float* b2   = (const float*)d_in[10];
    float* out = (float*)d_out;

    int M = in_sizes[0] / DD;      // 50000
    int E = in_sizes[2];           // 800000
    const int* src = ei;
    const int* dst = ei + E;

    cudaFuncSetAttribute(gemm_mma_kernel<false, false, false>,
                         cudaFuncAttributeMaxDynamicSharedMemorySize, SM_BYTES);
    cudaFuncSetAttribute(gemm_mma_kernel<true, true, true>,
                         cudaFuncAttributeMaxDynamicSharedMemorySize, SM_BYTES);

    dim3 ggemm((M + 63) / 64, 2);
    int gath_blocks = (M + 7) / 8;

    // ---- edge CSR build (shared by both layers) ----
    zero_kernel<<<(M + 255) / 256, 256>>>(M);
    hist_kernel<<<(E + 255) / 256, 256>>>(dst, E);
    scan_kernel<<<1, 1024>>>(M);
    fill_kernel<<<(E + 255) / 256, 256>>>(src, dst, et, E);

    // ---- layer 1 ----
    packb_kernel<<<(256 * DD + 255) / 256, 256>>>(W_I1, W_O1);
    relgemm_kernel<<<NRELMX, DD>>>(rel1, W_I1);
    gemm_mma_kernel<false, false, false><<<ggemm, 256, SM_BYTES>>>(x, b1, nullptr, M);
    gather_kernel<false><<<gath_blocks, 256>>>(nullptr, M);

    // ---- layer 2 (ReLU folded into A conversion) ----
    packb_kernel<<<(256 * DD + 255) / 256, 256>>>(W_I2, W_O2);
    relgemm_kernel<<<NRELMX, DD>>>(rel2, W_I2);
    gemm_mma_kernel<true, true, true><<<ggemm, 256, SM_BYTES>>>(nullptr, b2, out, M);
    gather_kernel<true><<<gath_blocks, 256>>>(out, M);
}

// round 9
// speedup vs baseline: 1.8104x; 1.2144x over previous
#include <cuda_runtime.h>
#include <cuda_bf16.h>
#include <cuda_fp16.h>
#include <cstdint>

#define NMAX   50000
#define EMAX   800000
#define DD     128
#define NRELMX 237

// SMEM layout (bytes): A/B bf16 row-major stride 136 elems (=272B)
#define SA      136
#define AHI_OFF 0
#define ALO_OFF 17408
#define BHI_OFF 34816
#define BLO_OFF 69632
#define SM_BYTES 104448
// staging (reuses A region): Ysh[64][72] fp16 (144B row), Hs[64][68] fp32
#define YS_OFF  0
#define HS_OFF  17408

// ---------------- static device scratch ------------------------------------
__device__ __half g_Yh[(size_t)NMAX * DD];    // X@W_I^T in fp16 (edge gather)
__device__ float  g_H[(size_t)NMAX * DD];     // layer-1 hidden
__device__ float  g_R[2][NRELMX * DD];        // rel @ W_I^T per layer (fp32)
__device__ __half g_Rh[2][NRELMX * DD];       // fp16 copies (edge gather)
__device__ int    g_cnt[NMAX];
__device__ int    g_rowstart[NMAX + 1];
__device__ int    g_edata[EMAX];              // packed (src<<8)|etype
// Pre-packed B images [256][136] bf16 (interleaved Y/Z cols), hi/lo
__device__ uint4 g_Bhi[(256 * SA * 2) / 16];
__device__ uint4 g_Blo[(256 * SA * 2) / 16];

// ---------------- PTX helpers ------------------------------------------------
__device__ __forceinline__ uint32_t smem_to_u32(const void* p) {
    uint32_t a;
    asm("{ .reg .u64 t; cvta.to.shared.u64 t, %1; cvt.u32.u64 %0, t; }" : "=r"(a) : "l"(p));
    return a;
}
__device__ __forceinline__ void ldmx4(uint32_t* r, uint32_t addr) {
    asm volatile("ldmatrix.sync.aligned.m8n8.x4.shared.b16 {%0,%1,%2,%3}, [%4];"
                 : "=r"(r[0]), "=r"(r[1]), "=r"(r[2]), "=r"(r[3]) : "r"(addr));
}
__device__ __forceinline__ void mma16816(float* d, const uint32_t* a, const uint32_t* b) {
    asm volatile(
        "mma.sync.aligned.m16n8k16.row.col.f32.bf16.bf16.f32 "
        "{%0,%1,%2,%3}, {%4,%5,%6,%7}, {%8,%9}, {%0,%1,%2,%3};"
        : "+f"(d[0]), "+f"(d[1]), "+f"(d[2]), "+f"(d[3])
        : "r"(a[0]), "r"(a[1]), "r"(a[2]), "r"(a[3]), "r"(b[0]), "r"(b[1]));
}
__device__ __forceinline__ uint32_t pack_bf2(__nv_bfloat16 a, __nv_bfloat16 b) {
    __nv_bfloat162 t(a, b);
    return *reinterpret_cast<uint32_t*>(&t);
}

// ---------------- B pack: [256][136] bf16 hi/lo, cols interleaved Y/Z -------
__global__ void packb_kernel(const float* __restrict__ W_I,
                             const float* __restrict__ W_O) {
    int idx = blockIdx.x * blockDim.x + threadIdx.x;  // 0..32767
    if (idx >= 256 * DD) return;
    int r = idx >> 7;
    int k = idx & 127;
    int c = r >> 1;
    float v = (r & 1) ? W_O[c * DD + k] : W_I[c * DD + k];
    __nv_bfloat16 hi = __float2bfloat16(v);
    __nv_bfloat16 lo = __float2bfloat16(v - __bfloat162float(hi));
    uint32_t off = (uint32_t)(r * SA + k) * 2u;
    *(__nv_bfloat16*)((char*)g_Bhi + off) = hi;
    *(__nv_bfloat16*)((char*)g_Blo + off) = lo;
}

// ---------------- R[layer][r][n] = sum_k rel[r][k] * W_I[n][k] --------------
__global__ void relgemm_kernel(const float* __restrict__ rel,
                               const float* __restrict__ W_I, int layer) {
    __shared__ float rr[DD];
    int r = blockIdx.x;
    int n = threadIdx.x;
    rr[n] = rel[r * DD + n];
    __syncthreads();
    const float4* w4 = (const float4*)(W_I + n * DD);
    float s = 0.f;
#pragma unroll
    for (int kk = 0; kk < DD / 4; kk++) {
        float4 wv = w4[kk];
        s += rr[4 * kk + 0] * wv.x + rr[4 * kk + 1] * wv.y +
             rr[4 * kk + 2] * wv.z + rr[4 * kk + 3] * wv.w;
    }
    g_R[layer][r * DD + n] = s;
    g_Rh[layer][r * DD + n] = __float2half(s);
}

// ---------------- edge CSR build --------------------------------------------
__global__ void zero_kernel(int M) {
    int i = blockIdx.x * blockDim.x + threadIdx.x;
    if (i < M) g_cnt[i] = 0;
}
__global__ void hist_kernel(const int* __restrict__ dst, int E) {
    int e = blockIdx.x * blockDim.x + threadIdx.x;
    if (e < E) atomicAdd(&g_cnt[dst[e]], 1);
}
__global__ __launch_bounds__(1024) void scan_kernel(int M) {
    __shared__ int ssum[1024];
    int t = threadIdx.x;
    const int CH = (M + 1023) / 1024;
    int beg = t * CH;
    int s = 0;
    for (int i = 0; i < CH; i++) {
        int idx = beg + i;
        if (idx < M) s += g_cnt[idx];
    }
    ssum[t] = s;
    __syncthreads();
    for (int off = 1; off < 1024; off <<= 1) {
        int v = (t >= off) ? ssum[t - off] : 0;
        __syncthreads();
        ssum[t] += v;
        __syncthreads();
    }
    int pre = (t == 0) ? 0 : ssum[t - 1];
    for (int i = 0; i < CH; i++) {
        int idx = beg + i;
        if (idx < M) {
            g_rowstart[idx] = pre;
            pre += g_cnt[idx];
        }
    }
    if (t == 1023) g_rowstart[M] = pre;
}
// fill post-increments g_rowstart[d]; afterwards g_rowstart[d] == row-end(d)
__global__ void fill_kernel(const int* __restrict__ src,
                            const int* __restrict__ dst,
                            const int* __restrict__ et, int E) {
    int e = blockIdx.x * blockDim.x + threadIdx.x;
    if (e >= E) return;
    int d = dst[e];
    int pos = atomicAdd(&g_rowstart[d], 1);
    g_edata[pos] = (src[e] << 8) | et[e];
}

// ---------------- HMMA GEMM: BM=64, BN=128 n' (64 real cols), occ 2 ---------
// D = Ahi*Bhi + Ahi*Blo + Alo*Bhi (3-term bf16 split, fp32 reg accum)
template <bool RELU, bool FROM_H, bool TO_OUT>
__global__ __launch_bounds__(256, 2)
void gemm_mma_kernel(const float* __restrict__ Ain,
                     const float* __restrict__ bias,
                     float* __restrict__ extout, int M, int layer) {
    extern __shared__ char smem[];
    uint32_t sb = smem_to_u32(smem);
    int tid = threadIdx.x;
    int wid = tid >> 5;
    int lane = tid & 31;
    int bm = blockIdx.x * 64;
    int bn = blockIdx.y;           // n-half (0/1)
    const float* A = FROM_H ? g_H : Ain;

    // ---- B copy: rows bn*128..+127 of packed images = 2176 uint4 each ----
    {
        const uint4* sbh = g_Bhi + (size_t)bn * 2176;
        const uint4* sbl = g_Blo + (size_t)bn * 2176;
        uint4* bh = (uint4*)(smem + BHI_OFF);
        uint4* bl = (uint4*)(smem + BLO_OFF);
#pragma unroll
        for (int i = 0; i < 9; i++) {
            int idx = tid + i * 256;
            if (idx < 2176) { bh[idx] = sbh[idx]; bl[idx] = sbl[idx]; }
        }
    }

    // ---- A load (coalesced) + bf16 hi/lo convert: 64x128 = 2048 float4 ----
#pragma unroll
    for (int i = 0; i < 8; i++) {
        int slot = tid + i * 256;
        int row = slot >> 5;
        int c4 = (slot & 31) * 4;
        int gm = bm + row;
        float4 v = make_float4(0.f, 0.f, 0.f, 0.f);
        if (gm < M) v = *(const float4*)(A + (size_t)gm * DD + c4);
        if (RELU) {
            v.x = fmaxf(v.x, 0.f); v.y = fmaxf(v.y, 0.f);
            v.z = fmaxf(v.z, 0.f); v.w = fmaxf(v.w, 0.f);
        }
        __nv_bfloat16 hx = __float2bfloat16(v.x);
        __nv_bfloat16 hy = __float2bfloat16(v.y);
        __nv_bfloat16 hz = __float2bfloat16(v.z);
        __nv_bfloat16 hw = __float2bfloat16(v.w);
        __nv_bfloat16 lx = __float2bfloat16(v.x - __bfloat162float(hx));
        __nv_bfloat16 ly = __float2bfloat16(v.y - __bfloat162float(hy));
        __nv_bfloat16 lz = __float2bfloat16(v.z - __bfloat162float(hz));
        __nv_bfloat16 lw = __float2bfloat16(v.w - __bfloat162float(hw));
        uint32_t off = (uint32_t)(row * SA + c4) * 2u;
        *(uint2*)(smem + AHI_OFF + off) = make_uint2(pack_bf2(hx, hy), pack_bf2(hz, hw));
        *(uint2*)(smem + ALO_OFF + off) = make_uint2(pack_bf2(lx, ly), pack_bf2(lz, lw));
    }
    __syncthreads();

    int wm = wid & 1;
    int wn = wid >> 1;
    int grp = lane >> 3;
    int r8 = lane & 7;

    float acc[2][4][4];
#pragma unroll
    for (int mt = 0; mt < 2; mt++)
#pragma unroll
        for (int nt = 0; nt < 4; nt++)
#pragma unroll
            for (int q = 0; q < 4; q++) acc[mt][nt][q] = 0.f;

#pragma unroll
    for (int term = 0; term < 3; term++) {
        uint32_t Ab = sb + ((term < 2) ? AHI_OFF : ALO_OFF);
        uint32_t Bb = sb + ((term == 1) ? BLO_OFF : BHI_OFF);
#pragma unroll
        for (int ks = 0; ks < 8; ks++) {
            int k0 = ks * 16;
            uint32_t afrag[2][4];
#pragma unroll
            for (int mt = 0; mt < 2; mt++) {
                int arow = wm * 32 + mt * 16 + (grp & 1) * 8 + r8;
                int acol = k0 + (grp >> 1) * 8;
                ldmx4(afrag[mt], Ab + (uint32_t)(arow * SA + acol) * 2u);
            }
            uint32_t bfrag[4][2];
#pragma unroll
            for (int np = 0; np < 2; np++) {
                int brow = wn * 32 + np * 16 + (grp >> 1) * 8 + r8;
                int bcol = k0 + (grp & 1) * 8;
                uint32_t t[4];
                ldmx4(t, Bb + (uint32_t)(brow * SA + bcol) * 2u);
                bfrag[np * 2][0] = t[0]; bfrag[np * 2][1] = t[1];
                bfrag[np * 2 + 1][0] = t[2]; bfrag[np * 2 + 1][1] = t[3];
            }
#pragma unroll
            for (int mt = 0; mt < 2; mt++)
#pragma unroll
                for (int nt = 0; nt < 4; nt++)
                    mma16816(acc[mt][nt], afrag[mt], bfrag[nt]);
        }
    }
    __syncthreads();   // done with A smem; reuse for staging

    // ---- stage: Ysh[64][72] fp16, Hs[64][68] fp32 ----
    __half* Ysh = (__half*)(smem + YS_OFF);
    float* Hs = (float*)(smem + HS_OFF);
    const float* Rb = g_R[layer];
#pragma unroll
    for (int nt = 0; nt < 4; nt++) {
        int cl = wn * 16 + nt * 4 + (lane & 3);
        int cg = bn * 64 + cl;
        float rb = bias[cg] - Rb[cg];
#pragma unroll
        for (int mt = 0; mt < 2; mt++) {
            int r0 = wm * 32 + mt * 16 + (lane >> 2);
            float y0 = acc[mt][nt][0], z0 = acc[mt][nt][1];
            float y1 = acc[mt][nt][2], z1 = acc[mt][nt][3];
            Ysh[r0 * 72 + cl] = __float2half(y0);
            Hs[r0 * 68 + cl] = y0 + z0 + rb;
            Ysh[(r0 + 8) * 72 + cl] = __float2half(y1);
            Hs[(r0 + 8) * 68 + cl] = y1 + z1 + rb;
        }
    }
    __syncthreads();

    // ---- coalesced copy-out ----
    float* H = TO_OUT ? extout : g_H;
#pragma unroll
    for (int i = 0; i < 4; i++) {
        int slot = tid + i * 256;
        int row = slot >> 4;
        int c4 = (slot & 15) * 4;
        int gm = bm + row;
        if (gm < M)
            *(float4*)&H[(size_t)gm * DD + bn * 64 + c4] = *(const float4*)&Hs[row * 68 + c4];
    }
#pragma unroll
    for (int i = 0; i < 4; i++) {
        int slot = tid + i * 256;
        int row = slot >> 4;
        int c4 = (slot & 15) * 4;
        int gm = bm + row;
        if (gm < M)
            *(uint2*)&g_Yh[(size_t)gm * DD + bn * 64 + c4] = *(const uint2*)&Ysh[row * 72 + c4];
    }
}

// ---------------- gather: H[n] += sum over in-edges of (Yh[src] - Rh[et]) ---
template <bool TO_OUT>
__global__ __launch_bounds__(256) void gather_kernel(float* __restrict__ extout, int M, int layer) {
    int node = blockIdx.x * 8 + (threadIdx.x >> 5);
    if (node >= M) return;
    int lane = threadIdx.x & 31;
    int beg = node ? __ldg(&g_rowstart[node - 1]) : 0;
    int end = __ldg(&g_rowstart[node]);
    const uint2* Yh = (const uint2*)g_Yh;   // 32 uint2 per row
    const uint2* Rh = (const uint2*)g_Rh[layer];
    float4 acc = make_float4(0.f, 0.f, 0.f, 0.f);
    int i = beg;
    for (; i + 1 < end; i += 2) {
        int e0 = __ldg(&g_edata[i]);
        int e1 = __ldg(&g_edata[i + 1]);
        uint2 y0 = __ldg(&Yh[(size_t)(e0 >> 8) * 32 + lane]);
        uint2 r0 = __ldg(&Rh[(size_t)(e0 & 255) * 32 + lane]);
        uint2 y1 = __ldg(&Yh[(size_t)(e1 >> 8) * 32 + lane]);
        uint2 r1 = __ldg(&Rh[(size_t)(e1 & 255) * 32 + lane]);
        float2 ya = __half22float2(*(__half2*)&y0.x), yb = __half22float2(*(__half2*)&y0.y);
        float2 ra = __half22float2(*(__half2*)&r0.x), rb = __half22float2(*(__half2*)&r0.y);
        float2 yc = __half22float2(*(__half2*)&y1.x), yd = __half22float2(*(__half2*)&y1.y);
        float2 rc = __half22float2(*(__half2*)&r1.x), rd = __half22float2(*(__half2*)&r1.y);
        acc.x += (ya.x - ra.x) + (yc.x - rc.x);
        acc.y += (ya.y - ra.y) + (yc.y - rc.y);
        acc.z += (yb.x - rb.x) + (yd.x - rd.x);
        acc.w += (yb.y - rb.y) + (yd.y - rd.y);
    }
    if (i < end) {
        int e0 = __ldg(&g_edata[i]);
        uint2 y0 = __ldg(&Yh[(size_t)(e0 >> 8) * 32 + lane]);
        uint2 r0 = __ldg(&Rh[(size_t)(e0 & 255) * 32 + lane]);
        float2 ya = __half22float2(*(__half2*)&y0.x), yb = __half22float2(*(__half2*)&y0.y);
        float2 ra = __half22float2(*(__half2*)&r0.x), rb = __half22float2(*(__half2*)&r0.y);
        acc.x += ya.x - ra.x;
        acc.y += ya.y - ra.y;
        acc.z += yb.x - rb.x;
        acc.w += yb.y - rb.y;
    }
    float* H = TO_OUT ? extout : g_H;
    int off = lane * 4;
    float4 h = *(float4*)&H[(size_t)node * DD + off];
    h.x += acc.x; h.y += acc.y; h.z += acc.z; h.w += acc.w;
    *(float4*)&H[(size_t)node * DD + off] = h;
}

// ---------------------------------------------------------------------------
extern "C" void kernel_launch(void* const* d_in, const int* in_sizes, int n_in,
                              void* d_out, int out_size) {
    const float* x    = (const float*)d_in[0];
    const int*   ei   = (const int*)d_in[1];
    const int*   et   = (const int*)d_in[2];
    const float* W_I1 = (const float*)d_in[3];
    const float* W_O1 = (const float*)d_in[4];
    const float* rel1 = (const float*)d_in[5];
    const float* b1   = (const float*)d_in[6];
    const float* W_I2 = (const float*)d_in[7];
    const float* W_O2 = (const float*)d_in[8];
    const float* rel2 = (const float*)d_in[9];
    const float* b2   = (const float*)d_in[10];
    float* out = (float*)d_out;

    int M = in_sizes[0] / DD;      // 50000
    int E = in_sizes[2];           // 800000
    const int* src = ei;
    const int* dst = ei + E;

    // lazily-created side stream + events (created on the uncaptured
    // correctness call; no device memory involved)
    static cudaStream_t s2 = nullptr;
    static cudaEvent_t evFork = nullptr, evJoin = nullptr;
    if (!s2) {
        cudaStreamCreateWithFlags(&s2, cudaStreamNonBlocking);
        cudaEventCreateWithFlags(&evFork, cudaEventDisableTiming);
        cudaEventCreateWithFlags(&evJoin, cudaEventDisableTiming);
    }

    cudaFuncSetAttribute(gemm_mma_kernel<false, false, false>,
                         cudaFuncAttributeMaxDynamicSharedMemorySize, SM_BYTES);
    cudaFuncSetAttribute(gemm_mma_kernel<true, true, true>,
                         cudaFuncAttributeMaxDynamicSharedMemorySize, SM_BYTES);

    dim3 ggemm((M + 63) / 64, 2);
    int gath_blocks = (M + 7) / 8;

    // ---- fork: CSR build on side stream (only gathers depend on it) ----
    cudaEventRecord(evFork, 0);
    cudaStreamWaitEvent(s2, evFork, 0);
    zero_kernel<<<(M + 255) / 256, 256, 0, s2>>>(M);
    hist_kernel<<<(E + 255) / 256, 256, 0, s2>>>(dst, E);
    scan_kernel<<<1, 1024, 0, s2>>>(M);
    fill_kernel<<<(E + 255) / 256, 256, 0, s2>>>(src, dst, et, E);
    cudaEventRecord(evJoin, s2);

    // ---- main stream: layer-1 GEMM chain (independent of CSR) ----
    packb_kernel<<<(256 * DD + 255) / 256, 256>>>(W_I1, W_O1);
    relgemm_kernel<<<NRELMX, DD>>>(rel1, W_I1, 0);
    gemm_mma_kernel<false, false, false><<<ggemm, 256, SM_BYTES>>>(x, b1, nullptr, M, 0);

    // layer-2 weight prep (writes layer-1-independent buffers: B images + R[1])
    packb_kernel<<<(256 * DD + 255) / 256, 256>>>(W_I2, W_O2);
    relgemm_kernel<<<NRELMX, DD>>>(rel2, W_I2, 1);

    // ---- join CSR, then gathers / layer-2 GEMM ----
    cudaStreamWaitEvent(0, evJoin, 0);
    gather_kernel<false><<<gath_blocks, 256>>>(nullptr, M, 0);
    gemm_mma_kernel<true, true, true><<<ggemm, 256, SM_BYTES>>>(nullptr, b2, out, M, 1);
    gather_kernel<true><<<gath_blocks, 256>>>(out, M, 1);
}

// round 10
// speedup vs baseline: 1.9644x; 1.0851x over previous
#include <cuda_runtime.h>
#include <cuda_bf16.h>
#include <cuda_fp16.h>
#include <cstdint>

#define NMAX   50000
#define EMAX   800000
#define DD     128
#define NRELMX 237

// SMEM layout (bytes): A/B bf16 row-major stride 136 elems (=272B)
#define SA      136
#define AHI_OFF 0
#define ALO_OFF 17408
#define BHI_OFF 34816
#define BLO_OFF 69632
#define SM_BYTES 104448
// staging (reuses A region): Ysh[64][72] fp16 (144B row), Hs[64][68] fp32
#define YS_OFF  0
#define HS_OFF  17408

// ---------------- static device scratch ------------------------------------
__device__ __half g_Yh[(size_t)NMAX * DD];    // X@W_I^T in fp16 (edge gather)
__device__ float  g_H[(size_t)NMAX * DD];     // layer-1 hidden
__device__ float  g_R[2][NRELMX * DD];        // rel @ W_I^T per layer (fp32)
__device__ __half g_Rh[2][NRELMX * DD];       // fp16 copies (edge gather)
__device__ int    g_cnt[NMAX];
__device__ int    g_rowstart[NMAX + 1];
__device__ int    g_edata[EMAX];              // packed (src<<8)|etype
// Pre-packed B images [256][136] bf16 (interleaved Y/Z cols), hi/lo
__device__ uint4 g_Bhi[(256 * SA * 2) / 16];
__device__ uint4 g_Blo[(256 * SA * 2) / 16];

// ---------------- PTX helpers ------------------------------------------------
__device__ __forceinline__ uint32_t smem_to_u32(const void* p) {
    uint32_t a;
    asm("{ .reg .u64 t; cvta.to.shared.u64 t, %1; cvt.u32.u64 %0, t; }" : "=r"(a) : "l"(p));
    return a;
}
__device__ __forceinline__ void ldmx4(uint32_t* r, uint32_t addr) {
    asm volatile("ldmatrix.sync.aligned.m8n8.x4.shared.b16 {%0,%1,%2,%3}, [%4];"
                 : "=r"(r[0]), "=r"(r[1]), "=r"(r[2]), "=r"(r[3]) : "r"(addr));
}
__device__ __forceinline__ void mma16816(float* d, const uint32_t* a, const uint32_t* b) {
    asm volatile(
        "mma.sync.aligned.m16n8k16.row.col.f32.bf16.bf16.f32 "
        "{%0,%1,%2,%3}, {%4,%5,%6,%7}, {%8,%9}, {%0,%1,%2,%3};"
        : "+f"(d[0]), "+f"(d[1]), "+f"(d[2]), "+f"(d[3])
        : "r"(a[0]), "r"(a[1]), "r"(a[2]), "r"(a[3]), "r"(b[0]), "r"(b[1]));
}
__device__ __forceinline__ uint32_t pack_bf2(__nv_bfloat16 a, __nv_bfloat16 b) {
    __nv_bfloat162 t(a, b);
    return *reinterpret_cast<uint32_t*>(&t);
}

// ---------------- B pack: [256][136] bf16 hi/lo, cols interleaved Y/Z -------
__global__ void packb_kernel(const float* __restrict__ W_I,
                             const float* __restrict__ W_O) {
    int idx = blockIdx.x * blockDim.x + threadIdx.x;  // 0..32767
    if (idx >= 256 * DD) return;
    int r = idx >> 7;
    int k = idx & 127;
    int c = r >> 1;
    float v = (r & 1) ? W_O[c * DD + k] : W_I[c * DD + k];
    __nv_bfloat16 hi = __float2bfloat16(v);
    __nv_bfloat16 lo = __float2bfloat16(v - __bfloat162float(hi));
    uint32_t off = (uint32_t)(r * SA + k) * 2u;
    *(__nv_bfloat16*)((char*)g_Bhi + off) = hi;
    *(__nv_bfloat16*)((char*)g_Blo + off) = lo;
}

// ---------------- R[layer][r][n] = sum_k rel[r][k] * W_I[n][k] --------------
__global__ void relgemm_kernel(const float* __restrict__ rel,
                               const float* __restrict__ W_I, int layer) {
    __shared__ float rr[DD];
    int r = blockIdx.x;
    int n = threadIdx.x;
    rr[n] = rel[r * DD + n];
    __syncthreads();
    const float4* w4 = (const float4*)(W_I + n * DD);
    float s = 0.f;
#pragma unroll
    for (int kk = 0; kk < DD / 4; kk++) {
        float4 wv = w4[kk];
        s += rr[4 * kk + 0] * wv.x + rr[4 * kk + 1] * wv.y +
             rr[4 * kk + 2] * wv.z + rr[4 * kk + 3] * wv.w;
    }
    g_R[layer][r * DD + n] = s;
    g_Rh[layer][r * DD + n] = __float2half(s);
}

// ---------------- edge CSR build --------------------------------------------
__global__ void zero_kernel(int M) {
    int i = blockIdx.x * blockDim.x + threadIdx.x;
    if (i < M) g_cnt[i] = 0;
}
__global__ void hist_kernel(const int* __restrict__ dst, int E) {
    int e = blockIdx.x * blockDim.x + threadIdx.x;
    if (e < E) atomicAdd(&g_cnt[dst[e]], 1);
}
__global__ __launch_bounds__(1024) void scan_kernel(int M) {
    __shared__ int ssum[1024];
    int t = threadIdx.x;
    const int CH = (M + 1023) / 1024;
    int beg = t * CH;
    int s = 0;
    for (int i = 0; i < CH; i++) {
        int idx = beg + i;
        if (idx < M) s += g_cnt[idx];
    }
    ssum[t] = s;
    __syncthreads();
    for (int off = 1; off < 1024; off <<= 1) {
        int v = (t >= off) ? ssum[t - off] : 0;
        __syncthreads();
        ssum[t] += v;
        __syncthreads();
    }
    int pre = (t == 0) ? 0 : ssum[t - 1];
    for (int i = 0; i < CH; i++) {
        int idx = beg + i;
        if (idx < M) {
            g_rowstart[idx] = pre;
            pre += g_cnt[idx];
        }
    }
    if (t == 1023) g_rowstart[M] = pre;
}
// fill post-increments g_rowstart[d]; afterwards g_rowstart[d] == row-end(d)
__global__ void fill_kernel(const int* __restrict__ src,
                            const int* __restrict__ dst,
                            const int* __restrict__ et, int E) {
    int e = blockIdx.x * blockDim.x + threadIdx.x;
    if (e >= E) return;
    int d = dst[e];
    int pos = atomicAdd(&g_rowstart[d], 1);
    g_edata[pos] = (src[e] << 8) | et[e];
}

// ---------------- HMMA GEMM: BM=64, BN=128 n' (64 real cols), occ 2 ---------
// D = Ahi*Bhi + Ahi*Blo + Alo*Bhi; ks-outer loop loads each frag set ONCE
template <bool RELU, bool FROM_H, bool TO_OUT>
__global__ __launch_bounds__(256, 2)
void gemm_mma_kernel(const float* __restrict__ Ain,
                     const float* __restrict__ bias,
                     float* __restrict__ extout, int M, int layer) {
    extern __shared__ char smem[];
    uint32_t sb = smem_to_u32(smem);
    int tid = threadIdx.x;
    int wid = tid >> 5;
    int lane = tid & 31;
    int bm = blockIdx.x * 64;
    int bn = blockIdx.y;           // n-half (0/1)
    const float* A = FROM_H ? g_H : Ain;

    // ---- B copy: rows bn*128..+127 of packed images = 2176 uint4 each ----
    {
        const uint4* sbh = g_Bhi + (size_t)bn * 2176;
        const uint4* sbl = g_Blo + (size_t)bn * 2176;
        uint4* bh = (uint4*)(smem + BHI_OFF);
        uint4* bl = (uint4*)(smem + BLO_OFF);
#pragma unroll
        for (int i = 0; i < 9; i++) {
            int idx = tid + i * 256;
            if (idx < 2176) { bh[idx] = sbh[idx]; bl[idx] = sbl[idx]; }
        }
    }

    // ---- A load (coalesced) + bf16 hi/lo convert: 64x128 = 2048 float4 ----
#pragma unroll
    for (int i = 0; i < 8; i++) {
        int slot = tid + i * 256;
        int row = slot >> 5;
        int c4 = (slot & 31) * 4;
        int gm = bm + row;
        float4 v = make_float4(0.f, 0.f, 0.f, 0.f);
        if (gm < M) v = *(const float4*)(A + (size_t)gm * DD + c4);
        if (RELU) {
            v.x = fmaxf(v.x, 0.f); v.y = fmaxf(v.y, 0.f);
            v.z = fmaxf(v.z, 0.f); v.w = fmaxf(v.w, 0.f);
        }
        __nv_bfloat16 hx = __float2bfloat16(v.x);
        __nv_bfloat16 hy = __float2bfloat16(v.y);
        __nv_bfloat16 hz = __float2bfloat16(v.z);
        __nv_bfloat16 hw = __float2bfloat16(v.w);
        __nv_bfloat16 lx = __float2bfloat16(v.x - __bfloat162float(hx));
        __nv_bfloat16 ly = __float2bfloat16(v.y - __bfloat162float(hy));
        __nv_bfloat16 lz = __float2bfloat16(v.z - __bfloat162float(hz));
        __nv_bfloat16 lw = __float2bfloat16(v.w - __bfloat162float(hw));
        uint32_t off = (uint32_t)(row * SA + c4) * 2u;
        *(uint2*)(smem + AHI_OFF + off) = make_uint2(pack_bf2(hx, hy), pack_bf2(hz, hw));
        *(uint2*)(smem + ALO_OFF + off) = make_uint2(pack_bf2(lx, ly), pack_bf2(lz, lw));
    }
    __syncthreads();

    int wm = wid & 1;
    int wn = wid >> 1;
    int grp = lane >> 3;
    int r8 = lane & 7;

    float acc[2][4][4];
#pragma unroll
    for (int mt = 0; mt < 2; mt++)
#pragma unroll
        for (int nt = 0; nt < 4; nt++)
#pragma unroll
            for (int q = 0; q < 4; q++) acc[mt][nt][q] = 0.f;

    // precomputed smem base offsets for this thread's ldmatrix addresses
    uint32_t a_off = sb + (uint32_t)((wm * 32 + (grp & 1) * 8 + r8) * SA + (grp >> 1) * 8) * 2u;
    uint32_t b_off = sb + (uint32_t)((wn * 32 + (grp >> 1) * 8 + r8) * SA + (grp & 1) * 8) * 2u;

#pragma unroll
    for (int ks = 0; ks < 8; ks++) {
        uint32_t kb = (uint32_t)(ks * 16 * 2);
        uint32_t afh[2][4], afl[2][4];
#pragma unroll
        for (int mt = 0; mt < 2; mt++) {
            uint32_t addr = a_off + (uint32_t)(mt * 16 * SA * 2) + kb;
            ldmx4(afh[mt], addr + AHI_OFF);
            ldmx4(afl[mt], addr + ALO_OFF);
        }
        uint32_t bfh[4][2], bfl[4][2];
#pragma unroll
        for (int np = 0; np < 2; np++) {
            uint32_t addr = b_off + (uint32_t)(np * 16 * SA * 2) + kb;
            uint32_t t[4];
            ldmx4(t, addr + BHI_OFF);
            bfh[np * 2][0] = t[0]; bfh[np * 2][1] = t[1];
            bfh[np * 2 + 1][0] = t[2]; bfh[np * 2 + 1][1] = t[3];
            ldmx4(t, addr + BLO_OFF);
            bfl[np * 2][0] = t[0]; bfl[np * 2][1] = t[1];
            bfl[np * 2 + 1][0] = t[2]; bfl[np * 2 + 1][1] = t[3];
        }
#pragma unroll
        for (int mt = 0; mt < 2; mt++)
#pragma unroll
            for (int nt = 0; nt < 4; nt++)
                mma16816(acc[mt][nt], afh[mt], bfh[nt]);
#pragma unroll
        for (int mt = 0; mt < 2; mt++)
#pragma unroll
            for (int nt = 0; nt < 4; nt++)
                mma16816(acc[mt][nt], afh[mt], bfl[nt]);
#pragma unroll
        for (int mt = 0; mt < 2; mt++)
#pragma unroll
            for (int nt = 0; nt < 4; nt++)
                mma16816(acc[mt][nt], afl[mt], bfh[nt]);
    }
    __syncthreads();   // done with A smem; reuse for staging

    // ---- stage: Ysh[64][72] fp16, Hs[64][68] fp32 ----
    __half* Ysh = (__half*)(smem + YS_OFF);
    float* Hs = (float*)(smem + HS_OFF);
    const float* Rb = g_R[layer];
#pragma unroll
    for (int nt = 0; nt < 4; nt++) {
        int cl = wn * 16 + nt * 4 + (lane & 3);
        int cg = bn * 64 + cl;
        float rb = bias[cg] - Rb[cg];
#pragma unroll
        for (int mt = 0; mt < 2; mt++) {
            int r0 = wm * 32 + mt * 16 + (lane >> 2);
            float y0 = acc[mt][nt][0], z0 = acc[mt][nt][1];
            float y1 = acc[mt][nt][2], z1 = acc[mt][nt][3];
            Ysh[r0 * 72 + cl] = __float2half(y0);
            Hs[r0 * 68 + cl] = y0 + z0 + rb;
            Ysh[(r0 + 8) * 72 + cl] = __float2half(y1);
            Hs[(r0 + 8) * 68 + cl] = y1 + z1 + rb;
        }
    }
    __syncthreads();

    // ---- coalesced copy-out ----
    float* H = TO_OUT ? extout : g_H;
#pragma unroll
    for (int i = 0; i < 4; i++) {
        int slot = tid + i * 256;
        int row = slot >> 4;
        int c4 = (slot & 15) * 4;
        int gm = bm + row;
        if (gm < M)
            *(float4*)&H[(size_t)gm * DD + bn * 64 + c4] = *(const float4*)&Hs[row * 68 + c4];
    }
#pragma unroll
    for (int i = 0; i < 4; i++) {
        int slot = tid + i * 256;
        int row = slot >> 4;
        int c4 = (slot & 15) * 4;
        int gm = bm + row;
        if (gm < M)
            *(uint2*)&g_Yh[(size_t)gm * DD + bn * 64 + c4] = *(const uint2*)&Ysh[row * 72 + c4];
    }
}

// ---------------- gather: H[n] += sum over in-edges of (Yh[src] - Rh[et]) ---
template <bool TO_OUT>
__global__ __launch_bounds__(256) void gather_kernel(float* __restrict__ extout, int M, int layer) {
    int node = blockIdx.x * 8 + (threadIdx.x >> 5);
    if (node >= M) return;
    int lane = threadIdx.x & 31;
    int beg = node ? __ldg(&g_rowstart[node - 1]) : 0;
    int end = __ldg(&g_rowstart[node]);
    const uint2* Yh = (const uint2*)g_Yh;   // 32 uint2 per row
    const uint2* Rh = (const uint2*)g_Rh[layer];
    float4 acc = make_float4(0.f, 0.f, 0.f, 0.f);
    int i = beg;
    for (; i + 1 < end; i += 2) {
        int e0 = __ldg(&g_edata[i]);
        int e1 = __ldg(&g_edata[i + 1]);
        uint2 y0 = __ldg(&Yh[(size_t)(e0 >> 8) * 32 + lane]);
        uint2 r0 = __ldg(&Rh[(size_t)(e0 & 255) * 32 + lane]);
        uint2 y1 = __ldg(&Yh[(size_t)(e1 >> 8) * 32 + lane]);
        uint2 r1 = __ldg(&Rh[(size_t)(e1 & 255) * 32 + lane]);
        float2 ya = __half22float2(*(__half2*)&y0.x), yb = __half22float2(*(__half2*)&y0.y);
        float2 ra = __half22float2(*(__half2*)&r0.x), rb = __half22float2(*(__half2*)&r0.y);
        float2 yc = __half22float2(*(__half2*)&y1.x), yd = __half22float2(*(__half2*)&y1.y);
        float2 rc = __half22float2(*(__half2*)&r1.x), rd = __half22float2(*(__half2*)&r1.y);
        acc.x += (ya.x - ra.x) + (yc.x - rc.x);
        acc.y += (ya.y - ra.y) + (yc.y - rc.y);
        acc.z += (yb.x - rb.x) + (yd.x - rd.x);
        acc.w += (yb.y - rb.y) + (yd.y - rd.y);
    }
    if (i < end) {
        int e0 = __ldg(&g_edata[i]);
        uint2 y0 = __ldg(&Yh[(size_t)(e0 >> 8) * 32 + lane]);
        uint2 r0 = __ldg(&Rh[(size_t)(e0 & 255) * 32 + lane]);
        float2 ya = __half22float2(*(__half2*)&y0.x), yb = __half22float2(*(__half2*)&y0.y);
        float2 ra = __half22float2(*(__half2*)&r0.x), rb = __half22float2(*(__half2*)&r0.y);
        acc.x += ya.x - ra.x;
        acc.y += ya.y - ra.y;
        acc.z += yb.x - rb.x;
        acc.w += yb.y - rb.y;
    }
    float* H = TO_OUT ? extout : g_H;
    int off = lane * 4;
    float4 h = *(float4*)&H[(size_t)node * DD + off];
    h.x += acc.x; h.y += acc.y; h.z += acc.z; h.w += acc.w;
    *(float4*)&H[(size_t)node * DD + off] = h;
}

// ---------------------------------------------------------------------------
extern "C" void kernel_launch(void* const* d_in, const int* in_sizes, int n_in,
                              void* d_out, int out_size) {
    const float* x    = (const float*)d_in[0];
    const int*   ei   = (const int*)d_in[1];
    const int*   et   = (const int*)d_in[2];
    const float* W_I1 = (const float*)d_in[3];
    const float* W_O1 = (const float*)d_in[4];
    const float* rel1 = (const float*)d_in[5];
    const float* b1   = (const float*)d_in[6];
    const float* W_I2 = (const float*)d_in[7];
    const float* W_O2 = (const float*)d_in[8];
    const float* rel2 = (const float*)d_in[9];
    const float* b2   = (const float*)d_in[10];
    float* out = (float*)d_out;

    int M = in_sizes[0] / DD;      // 50000
    int E = in_sizes[2];           // 800000
    const int* src = ei;
    const int* dst = ei + E;

    // lazily-created side stream + events (created on the uncaptured
    // correctness call; no device memory involved)
    static cudaStream_t s2 = nullptr;
    static cudaEvent_t evFork = nullptr, evJoin = nullptr;
    if (!s2) {
        cudaStreamCreateWithFlags(&s2, cudaStreamNonBlocking);
        cudaEventCreateWithFlags(&evFork, cudaEventDisableTiming);
        cudaEventCreateWithFlags(&evJoin, cudaEventDisableTiming);
    }

    cudaFuncSetAttribute(gemm_mma_kernel<false, false, false>,
                         cudaFuncAttributeMaxDynamicSharedMemorySize, SM_BYTES);
    cudaFuncSetAttribute(gemm_mma_kernel<true, true, true>,
                         cudaFuncAttributeMaxDynamicSharedMemorySize, SM_BYTES);

    dim3 ggemm((M + 63) / 64, 2);
    int gath_blocks = (M + 7) / 8;

    // ---- fork: CSR build on side stream (only gathers depend on it) ----
    cudaEventRecord(evFork, 0);
    cudaStreamWaitEvent(s2, evFork, 0);
    zero_kernel<<<(M + 255) / 256, 256, 0, s2>>>(M);
    hist_kernel<<<(E + 255) / 256, 256, 0, s2>>>(dst, E);
    scan_kernel<<<1, 1024, 0, s2>>>(M);
    fill_kernel<<<(E + 255) / 256, 256, 0, s2>>>(src, dst, et, E);
    cudaEventRecord(evJoin, s2);

    // ---- main stream: layer-1 GEMM chain (independent of CSR) ----
    packb_kernel<<<(256 * DD + 255) / 256, 256>>>(W_I1, W_O1);
    relgemm_kernel<<<NRELMX, DD>>>(rel1, W_I1, 0);
    gemm_mma_kernel<false, false, false><<<ggemm, 256, SM_BYTES>>>(x, b1, nullptr, M, 0);

    // layer-2 weight prep (writes layer-2 buffers: B images + R[1])
    packb_kernel<<<(256 * DD + 255) / 256, 256>>>(W_I2, W_O2);
    relgemm_kernel<<<NRELMX, DD>>>(rel2, W_I2, 1);

    // ---- join CSR, then gathers / layer-2 GEMM ----
    cudaStreamWaitEvent(0, evJoin, 0);
    gather_kernel<false><<<gath_blocks, 256>>>(nullptr, M, 0);
    gemm_mma_kernel<true, true, true><<<ggemm, 256, SM_BYTES>>>(nullptr, b2, out, M, 1);
    gather_kernel<true><<<gath_blocks, 256>>>(out, M, 1);
}

// round 11
// speedup vs baseline: 2.1191x; 1.0787x over previous
#include <cuda_runtime.h>
#include <cuda_bf16.h>
#include <cuda_fp16.h>
#include <cstdint>

#define NMAX   50000
#define EMAX   800000
#define DD     128
#define NRELMX 237

// SMEM layout (bytes): A/B fp16 row-major stride 136 elems (=272B)
#define SA      136
#define AHI_OFF 0
#define BHI_OFF 17408
#define BLO_OFF 52224
#define SM_BYTES 87040
// staging (reuses A/B region): Ysh[64][72] fp16, Hs[64][68] fp32
#define YS_OFF  0
#define HS_OFF  9216

// ---------------- static device scratch ------------------------------------
__device__ __half g_Yh[(size_t)NMAX * DD];    // X@W_I^T in fp16 (edge gather)
__device__ float  g_H[(size_t)NMAX * DD];     // layer-1 hidden
__device__ float  g_R[2][NRELMX * DD];        // rel @ W_I^T per layer (fp32)
__device__ __half g_Rh[2][NRELMX * DD];       // fp16 copies (edge gather)
__device__ int    g_cnt[NMAX];
__device__ int    g_rowstart[NMAX + 1];
__device__ int    g_edata[EMAX];              // packed (src<<8)|etype
// Pre-packed B images [256][136] fp16 (interleaved Y/Z cols), hi/lo
__device__ uint4 g_Bhi[(256 * SA * 2) / 16];
__device__ uint4 g_Blo[(256 * SA * 2) / 16];

// ---------------- PTX helpers ------------------------------------------------
__device__ __forceinline__ uint32_t smem_to_u32(const void* p) {
    uint32_t a;
    asm("{ .reg .u64 t; cvta.to.shared.u64 t, %1; cvt.u32.u64 %0, t; }" : "=r"(a) : "l"(p));
    return a;
}
__device__ __forceinline__ void ldmx4(uint32_t* r, uint32_t addr) {
    asm volatile("ldmatrix.sync.aligned.m8n8.x4.shared.b16 {%0,%1,%2,%3}, [%4];"
                 : "=r"(r[0]), "=r"(r[1]), "=r"(r[2]), "=r"(r[3]) : "r"(addr));
}
__device__ __forceinline__ void mma16816h(float* d, const uint32_t* a, const uint32_t* b) {
    asm volatile(
        "mma.sync.aligned.m16n8k16.row.col.f32.f16.f16.f32 "
        "{%0,%1,%2,%3}, {%4,%5,%6,%7}, {%8,%9}, {%0,%1,%2,%3};"
        : "+f"(d[0]), "+f"(d[1]), "+f"(d[2]), "+f"(d[3])
        : "r"(a[0]), "r"(a[1]), "r"(a[2]), "r"(a[3]), "r"(b[0]), "r"(b[1]));
}
__device__ __forceinline__ uint32_t pack_h2(__half a, __half b) {
    __half2 t = __halves2half2(a, b);
    return *reinterpret_cast<uint32_t*>(&t);
}

// ---------------- B pack: [256][136] fp16 hi/lo, cols interleaved Y/Z -------
__global__ void packb_kernel(const float* __restrict__ W_I,
                             const float* __restrict__ W_O) {
    int idx = blockIdx.x * blockDim.x + threadIdx.x;  // 0..32767
    if (idx >= 256 * DD) return;
    int r = idx >> 7;
    int k = idx & 127;
    int c = r >> 1;
    float v = (r & 1) ? W_O[c * DD + k] : W_I[c * DD + k];
    __half hi = __float2half(v);
    __half lo = __float2half(v - __half2float(hi));
    uint32_t off = (uint32_t)(r * SA + k) * 2u;
    *(__half*)((char*)g_Bhi + off) = hi;
    *(__half*)((char*)g_Blo + off) = lo;
}

// ---------------- R[layer][r][n] = sum_k rel[r][k] * W_I[n][k] --------------
__global__ void relgemm_kernel(const float* __restrict__ rel,
                               const float* __restrict__ W_I, int layer) {
    __shared__ float rr[DD];
    int r = blockIdx.x;
    int n = threadIdx.x;
    rr[n] = rel[r * DD + n];
    __syncthreads();
    const float4* w4 = (const float4*)(W_I + n * DD);
    float s = 0.f;
#pragma unroll
    for (int kk = 0; kk < DD / 4; kk++) {
        float4 wv = w4[kk];
        s += rr[4 * kk + 0] * wv.x + rr[4 * kk + 1] * wv.y +
             rr[4 * kk + 2] * wv.z + rr[4 * kk + 3] * wv.w;
    }
    g_R[layer][r * DD + n] = s;
    g_Rh[layer][r * DD + n] = __float2half(s);
}

// ---------------- edge CSR build --------------------------------------------
__global__ void zero_kernel(int M) {
    int i = blockIdx.x * blockDim.x + threadIdx.x;
    if (i < M) g_cnt[i] = 0;
}
__global__ void hist_kernel(const int* __restrict__ dst, int E) {
    int e = blockIdx.x * blockDim.x + threadIdx.x;
    if (e < E) atomicAdd(&g_cnt[dst[e]], 1);
}
__global__ __launch_bounds__(1024) void scan_kernel(int M) {
    __shared__ int ssum[1024];
    int t = threadIdx.x;
    const int CH = (M + 1023) / 1024;
    int beg = t * CH;
    int s = 0;
    for (int i = 0; i < CH; i++) {
        int idx = beg + i;
        if (idx < M) s += g_cnt[idx];
    }
    ssum[t] = s;
    __syncthreads();
    for (int off = 1; off < 1024; off <<= 1) {
        int v = (t >= off) ? ssum[t - off] : 0;
        __syncthreads();
        ssum[t] += v;
        __syncthreads();
    }
    int pre = (t == 0) ? 0 : ssum[t - 1];
    for (int i = 0; i < CH; i++) {
        int idx = beg + i;
        if (idx < M) {
            g_rowstart[idx] = pre;
            pre += g_cnt[idx];
        }
    }
    if (t == 1023) g_rowstart[M] = pre;
}
// fill post-increments g_rowstart[d]; afterwards g_rowstart[d] == row-end(d)
__global__ void fill_kernel(const int* __restrict__ src,
                            const int* __restrict__ dst,
                            const int* __restrict__ et, int E) {
    int e = blockIdx.x * blockDim.x + threadIdx.x;
    if (e >= E) return;
    int d = dst[e];
    int pos = atomicAdd(&g_rowstart[d], 1);
    g_edata[pos] = (src[e] << 8) | et[e];
}

// ---------------- HMMA GEMM: BM=64, BN=128 n' (64 real cols), occ 2 ---------
// 2-term fp16 split: D = Ahi*Bhi + Ahi*Blo (fp32 accum)
template <bool RELU, bool FROM_H, bool TO_OUT>
__global__ __launch_bounds__(256, 2)
void gemm_mma_kernel(const float* __restrict__ Ain,
                     const float* __restrict__ bias,
                     float* __restrict__ extout, int M, int layer) {
    extern __shared__ char smem[];
    uint32_t sb = smem_to_u32(smem);
    int tid = threadIdx.x;
    int wid = tid >> 5;
    int lane = tid & 31;
    int bm = blockIdx.x * 64;
    int bn = blockIdx.y;           // n-half (0/1)
    const float* A = FROM_H ? g_H : Ain;

    // ---- B copy: rows bn*128..+127 of packed images = 2176 uint4 each ----
    {
        const uint4* sbh = g_Bhi + (size_t)bn * 2176;
        const uint4* sbl = g_Blo + (size_t)bn * 2176;
        uint4* bh = (uint4*)(smem + BHI_OFF);
        uint4* bl = (uint4*)(smem + BLO_OFF);
#pragma unroll
        for (int i = 0; i < 9; i++) {
            int idx = tid + i * 256;
            if (idx < 2176) { bh[idx] = sbh[idx]; bl[idx] = sbl[idx]; }
        }
    }

    // ---- A load (coalesced) + fp16 convert: 64x128 = 2048 float4 ----
#pragma unroll
    for (int i = 0; i < 8; i++) {
        int slot = tid + i * 256;
        int row = slot >> 5;
        int c4 = (slot & 31) * 4;
        int gm = bm + row;
        float4 v = make_float4(0.f, 0.f, 0.f, 0.f);
        if (gm < M) v = *(const float4*)(A + (size_t)gm * DD + c4);
        if (RELU) {
            v.x = fmaxf(v.x, 0.f); v.y = fmaxf(v.y, 0.f);
            v.z = fmaxf(v.z, 0.f); v.w = fmaxf(v.w, 0.f);
        }
        uint32_t off = (uint32_t)(row * SA + c4) * 2u;
        *(uint2*)(smem + AHI_OFF + off) =
            make_uint2(pack_h2(__float2half(v.x), __float2half(v.y)),
                       pack_h2(__float2half(v.z), __float2half(v.w)));
    }
    __syncthreads();

    int wm = wid & 1;
    int wn = wid >> 1;
    int grp = lane >> 3;
    int r8 = lane & 7;

    float acc[2][4][4];
#pragma unroll
    for (int mt = 0; mt < 2; mt++)
#pragma unroll
        for (int nt = 0; nt < 4; nt++)
#pragma unroll
            for (int q = 0; q < 4; q++) acc[mt][nt][q] = 0.f;

    // precomputed smem base offsets for this thread's ldmatrix addresses
    uint32_t a_off = sb + (uint32_t)((wm * 32 + (grp & 1) * 8 + r8) * SA + (grp >> 1) * 8) * 2u;
    uint32_t b_off = sb + (uint32_t)((wn * 32 + (grp >> 1) * 8 + r8) * SA + (grp & 1) * 8) * 2u;

#pragma unroll
    for (int ks = 0; ks < 8; ks++) {
        uint32_t kb = (uint32_t)(ks * 16 * 2);
        uint32_t afh[2][4];
#pragma unroll
        for (int mt = 0; mt < 2; mt++)
            ldmx4(afh[mt], a_off + (uint32_t)(mt * 16 * SA * 2) + kb + AHI_OFF);
        uint32_t bfh[4][2], bfl[4][2];
#pragma unroll
        for (int np = 0; np < 2; np++) {
            uint32_t addr = b_off + (uint32_t)(np * 16 * SA * 2) + kb;
            uint32_t t[4];
            ldmx4(t, addr + BHI_OFF);
            bfh[np * 2][0] = t[0]; bfh[np * 2][1] = t[1];
            bfh[np * 2 + 1][0] = t[2]; bfh[np * 2 + 1][1] = t[3];
            ldmx4(t, addr + BLO_OFF);
            bfl[np * 2][0] = t[0]; bfl[np * 2][1] = t[1];
            bfl[np * 2 + 1][0] = t[2]; bfl[np * 2 + 1][1] = t[3];
        }
#pragma unroll
        for (int mt = 0; mt < 2; mt++)
#pragma unroll
            for (int nt = 0; nt < 4; nt++)
                mma16816h(acc[mt][nt], afh[mt], bfh[nt]);
#pragma unroll
        for (int mt = 0; mt < 2; mt++)
#pragma unroll
            for (int nt = 0; nt < 4; nt++)
                mma16816h(acc[mt][nt], afh[mt], bfl[nt]);
    }
    __syncthreads();   // done with A/B smem; reuse for staging

    // ---- stage: Ysh[64][72] fp16, Hs[64][68] fp32 ----
    __half* Ysh = (__half*)(smem + YS_OFF);
    float* Hs = (float*)(smem + HS_OFF);
    const float* Rb = g_R[layer];
#pragma unroll
    for (int nt = 0; nt < 4; nt++) {
        int cl = wn * 16 + nt * 4 + (lane & 3);
        int cg = bn * 64 + cl;
        float rb = bias[cg] - Rb[cg];
#pragma unroll
        for (int mt = 0; mt < 2; mt++) {
            int r0 = wm * 32 + mt * 16 + (lane >> 2);
            float y0 = acc[mt][nt][0], z0 = acc[mt][nt][1];
            float y1 = acc[mt][nt][2], z1 = acc[mt][nt][3];
            Ysh[r0 * 72 + cl] = __float2half(y0);
            Hs[r0 * 68 + cl] = y0 + z0 + rb;
            Ysh[(r0 + 8) * 72 + cl] = __float2half(y1);
            Hs[(r0 + 8) * 68 + cl] = y1 + z1 + rb;
        }
    }
    __syncthreads();

    // ---- coalesced copy-out ----
    float* H = TO_OUT ? extout : g_H;
#pragma unroll
    for (int i = 0; i < 4; i++) {
        int slot = tid + i * 256;
        int row = slot >> 4;
        int c4 = (slot & 15) * 4;
        int gm = bm + row;
        if (gm < M)
            *(float4*)&H[(size_t)gm * DD + bn * 64 + c4] = *(const float4*)&Hs[row * 68 + c4];
    }
#pragma unroll
    for (int i = 0; i < 4; i++) {
        int slot = tid + i * 256;
        int row = slot >> 4;
        int c4 = (slot & 15) * 4;
        int gm = bm + row;
        if (gm < M)
            *(uint2*)&g_Yh[(size_t)gm * DD + bn * 64 + c4] = *(const uint2*)&Ysh[row * 72 + c4];
    }
}

// ---------------- gather: H[n] += sum over in-edges of (Yh[src] - Rh[et]) ---
template <bool TO_OUT>
__global__ __launch_bounds__(256) void gather_kernel(float* __restrict__ extout, int M, int layer) {
    int node = blockIdx.x * 8 + (threadIdx.x >> 5);
    if (node >= M) return;
    int lane = threadIdx.x & 31;
    int beg = node ? __ldg(&g_rowstart[node - 1]) : 0;
    int end = __ldg(&g_rowstart[node]);
    const uint2* Yh = (const uint2*)g_Yh;   // 32 uint2 per row
    const uint2* Rh = (const uint2*)g_Rh[layer];
    float4 acc = make_float4(0.f, 0.f, 0.f, 0.f);
    int i = beg;
    for (; i + 1 < end; i += 2) {
        int e0 = __ldg(&g_edata[i]);
        int e1 = __ldg(&g_edata[i + 1]);
        uint2 y0 = __ldg(&Yh[(size_t)(e0 >> 8) * 32 + lane]);
        uint2 r0 = __ldg(&Rh[(size_t)(e0 & 255) * 32 + lane]);
        uint2 y1 = __ldg(&Yh[(size_t)(e1 >> 8) * 32 + lane]);
        uint2 r1 = __ldg(&Rh[(size_t)(e1 & 255) * 32 + lane]);
        float2 ya = __half22float2(*(__half2*)&y0.x), yb = __half22float2(*(__half2*)&y0.y);
        float2 ra = __half22float2(*(__half2*)&r0.x), rb = __half22float2(*(__half2*)&r0.y);
        float2 yc = __half22float2(*(__half2*)&y1.x), yd = __half22float2(*(__half2*)&y1.y);
        float2 rc = __half22float2(*(__half2*)&r1.x), rd = __half22float2(*(__half2*)&r1.y);
        acc.x += (ya.x - ra.x) + (yc.x - rc.x);
        acc.y += (ya.y - ra.y) + (yc.y - rc.y);
        acc.z += (yb.x - rb.x) + (yd.x - rd.x);
        acc.w += (yb.y - rb.y) + (yd.y - rd.y);
    }
    if (i < end) {
        int e0 = __ldg(&g_edata[i]);
        uint2 y0 = __ldg(&Yh[(size_t)(e0 >> 8) * 32 + lane]);
        uint2 r0 = __ldg(&Rh[(size_t)(e0 & 255) * 32 + lane]);
        float2 ya = __half22float2(*(__half2*)&y0.x), yb = __half22float2(*(__half2*)&y0.y);
        float2 ra = __half22float2(*(__half2*)&r0.x), rb = __half22float2(*(__half2*)&r0.y);
        acc.x += ya.x - ra.x;
        acc.y += ya.y - ra.y;
        acc.z += yb.x - rb.x;
        acc.w += yb.y - rb.y;
    }
    float* H = TO_OUT ? extout : g_H;
    int off = lane * 4;
    float4 h = *(float4*)&H[(size_t)node * DD + off];
    h.x += acc.x; h.y += acc.y; h.z += acc.z; h.w += acc.w;
    *(float4*)&H[(size_t)node * DD + off] = h;
}

// ---------------------------------------------------------------------------
extern "C" void kernel_launch(void* const* d_in, const int* in_sizes, int n_in,
                              void* d_out, int out_size) {
    const float* x    = (const float*)d_in[0];
    const int*   ei   = (const int*)d_in[1];
    const int*   et   = (const int*)d_in[2];
    const float* W_I1 = (const float*)d_in[3];
    const float* W_O1 = (const float*)d_in[4];
    const float* rel1 = (const float*)d_in[5];
    const float* b1   = (const float*)d_in[6];
    const float* W_I2 = (const float*)d_in[7];
    const float* W_O2 = (const float*)d_in[8];
    const float* rel2 = (const float*)d_in[9];
    const float* b2   = (const float*)d_in[10];
    float* out = (float*)d_out;

    int M = in_sizes[0] / DD;      // 50000
    int E = in_sizes[2];           // 800000
    const int* src = ei;
    const int* dst = ei + E;

    // lazily-created side stream + events (created on the uncaptured
    // correctness call; no device memory involved)
    static cudaStream_t s2 = nullptr;
    static cudaEvent_t evFork = nullptr, evJoin = nullptr;
    if (!s2) {
        cudaStreamCreateWithFlags(&s2, cudaStreamNonBlocking);
        cudaEventCreateWithFlags(&evFork, cudaEventDisableTiming);
        cudaEventCreateWithFlags(&evJoin, cudaEventDisableTiming);
    }

    cudaFuncSetAttribute(gemm_mma_kernel<false, false, false>,
                         cudaFuncAttributeMaxDynamicSharedMemorySize, SM_BYTES);
    cudaFuncSetAttribute(gemm_mma_kernel<true, true, true>,
                         cudaFuncAttributeMaxDynamicSharedMemorySize, SM_BYTES);

    dim3 ggemm((M + 63) / 64, 2);
    int gath_blocks = (M + 7) / 8;

    // ---- fork: CSR build on side stream (only gathers depend on it) ----
    cudaEventRecord(evFork, 0);
    cudaStreamWaitEvent(s2, evFork, 0);
    zero_kernel<<<(M + 255) / 256, 256, 0, s2>>>(M);
    hist_kernel<<<(E + 255) / 256, 256, 0, s2>>>(dst, E);
    scan_kernel<<<1, 1024, 0, s2>>>(M);
    fill_kernel<<<(E + 255) / 256, 256, 0, s2>>>(src, dst, et, E);
    cudaEventRecord(evJoin, s2);

    // ---- main stream: layer-1 GEMM chain (independent of CSR) ----
    packb_kernel<<<(256 * DD + 255) / 256, 256>>>(W_I1, W_O1);
    relgemm_kernel<<<NRELMX, DD>>>(rel1, W_I1, 0);
    gemm_mma_kernel<false, false, false><<<ggemm, 256, SM_BYTES>>>(x, b1, nullptr, M, 0);

    // layer-2 weight prep (writes layer-2 buffers: B images + R[1])
    packb_kernel<<<(256 * DD + 255) / 256, 256>>>(W_I2, W_O2);
    relgemm_kernel<<<NRELMX, DD>>>(rel2, W_I2, 1);

    // ---- join CSR, then gathers / layer-2 GEMM ----
    cudaStreamWaitEvent(0, evJoin, 0);
    gather_kernel<false><<<gath_blocks, 256>>>(nullptr, M, 0);
    gemm_mma_kernel<true, true, true><<<ggemm, 256, SM_BYTES>>>(nullptr, b2, out, M, 1);
    gather_kernel<true><<<gath_blocks, 256>>>(out, M, 1);
}

// round 12
// speedup vs baseline: 2.2336x; 1.0540x over previous
#include <cuda_runtime.h>
#include <cuda_bf16.h>
#include <cuda_fp16.h>
#include <cstdint>

#define NMAX   50000
#define EMAX   800000
#define DD     128
#define NRELMX 237

// SMEM layout (bytes): A/B fp16 row-major stride 136 elems (=272B)
#define SA      136
#define AHI_OFF 0
#define BHI_OFF 17408
#define SM_BYTES 52224
// staging (reuses A/B region): Ysh[64][72] fp16, Hs[64][68] fp32
#define YS_OFF  0
#define HS_OFF  9216

// ---------------- static device scratch ------------------------------------
__device__ __half g_Yh[(size_t)NMAX * DD];    // X@W_I^T in fp16 (edge gather)
__device__ float  g_H[(size_t)NMAX * DD];     // layer-1 hidden
__device__ float  g_R[2][NRELMX * DD];        // rel @ W_I^T per layer (fp32)
__device__ __half g_Rh[2][NRELMX * DD];       // fp16 copies (edge gather)
__device__ int    g_cnt[NMAX];
__device__ int    g_rowstart[NMAX + 1];
__device__ int    g_edata[EMAX];              // packed (src<<8)|etype
// Pre-packed B image [256][136] fp16 (interleaved Y/Z cols)
__device__ uint4 g_Bhi[(256 * SA * 2) / 16];

// ---------------- PTX helpers ------------------------------------------------
__device__ __forceinline__ uint32_t smem_to_u32(const void* p) {
    uint32_t a;
    asm("{ .reg .u64 t; cvta.to.shared.u64 t, %1; cvt.u32.u64 %0, t; }" : "=r"(a) : "l"(p));
    return a;
}
__device__ __forceinline__ void ldmx4(uint32_t* r, uint32_t addr) {
    asm volatile("ldmatrix.sync.aligned.m8n8.x4.shared.b16 {%0,%1,%2,%3}, [%4];"
                 : "=r"(r[0]), "=r"(r[1]), "=r"(r[2]), "=r"(r[3]) : "r"(addr));
}
__device__ __forceinline__ void mma16816h(float* d, const uint32_t* a, const uint32_t* b) {
    asm volatile(
        "mma.sync.aligned.m16n8k16.row.col.f32.f16.f16.f32 "
        "{%0,%1,%2,%3}, {%4,%5,%6,%7}, {%8,%9}, {%0,%1,%2,%3};"
        : "+f"(d[0]), "+f"(d[1]), "+f"(d[2]), "+f"(d[3])
        : "r"(a[0]), "r"(a[1]), "r"(a[2]), "r"(a[3]), "r"(b[0]), "r"(b[1]));
}
__device__ __forceinline__ uint32_t pack_h2(__half a, __half b) {
    __half2 t = __halves2half2(a, b);
    return *reinterpret_cast<uint32_t*>(&t);
}

// ---------------- B pack: [256][136] fp16, cols interleaved Y/Z -------------
__global__ void packb_kernel(const float* __restrict__ W_I,
                             const float* __restrict__ W_O) {
    int idx = blockIdx.x * blockDim.x + threadIdx.x;  // 0..32767
    if (idx >= 256 * DD) return;
    int r = idx >> 7;
    int k = idx & 127;
    int c = r >> 1;
    float v = (r & 1) ? W_O[c * DD + k] : W_I[c * DD + k];
    uint32_t off = (uint32_t)(r * SA + k) * 2u;
    *(__half*)((char*)g_Bhi + off) = __float2half(v);
}

// ---------------- R[layer][r][n] = sum_k rel[r][k] * W_I[n][k] --------------
__global__ void relgemm_kernel(const float* __restrict__ rel,
                               const float* __restrict__ W_I, int layer) {
    __shared__ float rr[DD];
    int r = blockIdx.x;
    int n = threadIdx.x;
    rr[n] = rel[r * DD + n];
    __syncthreads();
    const float4* w4 = (const float4*)(W_I + n * DD);
    float s = 0.f;
#pragma unroll
    for (int kk = 0; kk < DD / 4; kk++) {
        float4 wv = w4[kk];
        s += rr[4 * kk + 0] * wv.x + rr[4 * kk + 1] * wv.y +
             rr[4 * kk + 2] * wv.z + rr[4 * kk + 3] * wv.w;
    }
    g_R[layer][r * DD + n] = s;
    g_Rh[layer][r * DD + n] = __float2half(s);
}

// ---------------- edge CSR build --------------------------------------------
__global__ void zero_kernel(int M) {
    int i = blockIdx.x * blockDim.x + threadIdx.x;
    if (i < M) g_cnt[i] = 0;
}
__global__ void hist_kernel(const int* __restrict__ dst, int E) {
    int e = blockIdx.x * blockDim.x + threadIdx.x;
    if (e < E) atomicAdd(&g_cnt[dst[e]], 1);
}
__global__ __launch_bounds__(1024) void scan_kernel(int M) {
    __shared__ int ssum[1024];
    int t = threadIdx.x;
    const int CH = (M + 1023) / 1024;
    int beg = t * CH;
    int s = 0;
    for (int i = 0; i < CH; i++) {
        int idx = beg + i;
        if (idx < M) s += g_cnt[idx];
    }
    ssum[t] = s;
    __syncthreads();
    for (int off = 1; off < 1024; off <<= 1) {
        int v = (t >= off) ? ssum[t - off] : 0;
        __syncthreads();
        ssum[t] += v;
        __syncthreads();
    }
    int pre = (t == 0) ? 0 : ssum[t - 1];
    for (int i = 0; i < CH; i++) {
        int idx = beg + i;
        if (idx < M) {
            g_rowstart[idx] = pre;
            pre += g_cnt[idx];
        }
    }
    if (t == 1023) g_rowstart[M] = pre;
}
// fill post-increments g_rowstart[d]; afterwards g_rowstart[d] == row-end(d)
__global__ void fill_kernel(const int* __restrict__ src,
                            const int* __restrict__ dst,
                            const int* __restrict__ et, int E) {
    int e = blockIdx.x * blockDim.x + threadIdx.x;
    if (e >= E) return;
    int d = dst[e];
    int pos = atomicAdd(&g_rowstart[d], 1);
    g_edata[pos] = (src[e] << 8) | et[e];
}

// ---------------- HMMA GEMM: BM=64, BN=128 n' (64 real cols), occ 3 ---------
// single-term fp16: D = fp16(A) * fp16(B), fp32 accum
template <bool RELU, bool FROM_H, bool TO_OUT>
__global__ __launch_bounds__(256, 3)
void gemm_mma_kernel(const float* __restrict__ Ain,
                     const float* __restrict__ bias,
                     float* __restrict__ extout, int M, int layer) {
    extern __shared__ char smem[];
    uint32_t sb = smem_to_u32(smem);
    int tid = threadIdx.x;
    int wid = tid >> 5;
    int lane = tid & 31;
    int bm = blockIdx.x * 64;
    int bn = blockIdx.y;           // n-half (0/1)
    const float* A = FROM_H ? g_H : Ain;

    // ---- B copy: rows bn*128..+127 of packed image = 2176 uint4 ----
    {
        const uint4* sbh = g_Bhi + (size_t)bn * 2176;
        uint4* bh = (uint4*)(smem + BHI_OFF);
#pragma unroll
        for (int i = 0; i < 9; i++) {
            int idx = tid + i * 256;
            if (idx < 2176) bh[idx] = sbh[idx];
        }
    }

    // ---- A load (coalesced) + fp16 convert: 64x128 = 2048 float4 ----
#pragma unroll
    for (int i = 0; i < 8; i++) {
        int slot = tid + i * 256;
        int row = slot >> 5;
        int c4 = (slot & 31) * 4;
        int gm = bm + row;
        float4 v = make_float4(0.f, 0.f, 0.f, 0.f);
        if (gm < M) v = *(const float4*)(A + (size_t)gm * DD + c4);
        if (RELU) {
            v.x = fmaxf(v.x, 0.f); v.y = fmaxf(v.y, 0.f);
            v.z = fmaxf(v.z, 0.f); v.w = fmaxf(v.w, 0.f);
        }
        uint32_t off = (uint32_t)(row * SA + c4) * 2u;
        *(uint2*)(smem + AHI_OFF + off) =
            make_uint2(pack_h2(__float2half(v.x), __float2half(v.y)),
                       pack_h2(__float2half(v.z), __float2half(v.w)));
    }
    __syncthreads();

    int wm = wid & 1;
    int wn = wid >> 1;
    int grp = lane >> 3;
    int r8 = lane & 7;

    float acc[2][4][4];
#pragma unroll
    for (int mt = 0; mt < 2; mt++)
#pragma unroll
        for (int nt = 0; nt < 4; nt++)
#pragma unroll
            for (int q = 0; q < 4; q++) acc[mt][nt][q] = 0.f;

    // precomputed smem base offsets for this thread's ldmatrix addresses
    uint32_t a_off = sb + (uint32_t)((wm * 32 + (grp & 1) * 8 + r8) * SA + (grp >> 1) * 8) * 2u;
    uint32_t b_off = sb + (uint32_t)((wn * 32 + (grp >> 1) * 8 + r8) * SA + (grp & 1) * 8) * 2u;

#pragma unroll
    for (int ks = 0; ks < 8; ks++) {
        uint32_t kb = (uint32_t)(ks * 16 * 2);
        uint32_t afh[2][4];
#pragma unroll
        for (int mt = 0; mt < 2; mt++)
            ldmx4(afh[mt], a_off + (uint32_t)(mt * 16 * SA * 2) + kb + AHI_OFF);
        uint32_t bfh[4][2];
#pragma unroll
        for (int np = 0; np < 2; np++) {
            uint32_t addr = b_off + (uint32_t)(np * 16 * SA * 2) + kb;
            uint32_t t[4];
            ldmx4(t, addr + BHI_OFF);
            bfh[np * 2][0] = t[0]; bfh[np * 2][1] = t[1];
            bfh[np * 2 + 1][0] = t[2]; bfh[np * 2 + 1][1] = t[3];
        }
#pragma unroll
        for (int mt = 0; mt < 2; mt++)
#pragma unroll
            for (int nt = 0; nt < 4; nt++)
                mma16816h(acc[mt][nt], afh[mt], bfh[nt]);
    }
    __syncthreads();   // done with A/B smem; reuse for staging

    // ---- stage: Ysh[64][72] fp16, Hs[64][68] fp32 ----
    __half* Ysh = (__half*)(smem + YS_OFF);
    float* Hs = (float*)(smem + HS_OFF);
    const float* Rb = g_R[layer];
#pragma unroll
    for (int nt = 0; nt < 4; nt++) {
        int cl = wn * 16 + nt * 4 + (lane & 3);
        int cg = bn * 64 + cl;
        float rb = bias[cg] - Rb[cg];
#pragma unroll
        for (int mt = 0; mt < 2; mt++) {
            int r0 = wm * 32 + mt * 16 + (lane >> 2);
            float y0 = acc[mt][nt][0], z0 = acc[mt][nt][1];
            float y1 = acc[mt][nt][2], z1 = acc[mt][nt][3];
            Ysh[r0 * 72 + cl] = __float2half(y0);
            Hs[r0 * 68 + cl] = y0 + z0 + rb;
            Ysh[(r0 + 8) * 72 + cl] = __float2half(y1);
            Hs[(r0 + 8) * 68 + cl] = y1 + z1 + rb;
        }
    }
    __syncthreads();

    // ---- coalesced copy-out ----
    float* H = TO_OUT ? extout : g_H;
#pragma unroll
    for (int i = 0; i < 4; i++) {
        int slot = tid + i * 256;
        int row = slot >> 4;
        int c4 = (slot & 15) * 4;
        int gm = bm + row;
        if (gm < M)
            *(float4*)&H[(size_t)gm * DD + bn * 64 + c4] = *(const float4*)&Hs[row * 68 + c4];
    }
#pragma unroll
    for (int i = 0; i < 4; i++) {
        int slot = tid + i * 256;
        int row = slot >> 4;
        int c4 = (slot & 15) * 4;
        int gm = bm + row;
        if (gm < M)
            *(uint2*)&g_Yh[(size_t)gm * DD + bn * 64 + c4] = *(const uint2*)&Ysh[row * 72 + c4];
    }
}

// ---------------- gather: H[n] += sum over in-edges of (Yh[src] - Rh[et]) ---
template <bool TO_OUT>
__global__ __launch_bounds__(256) void gather_kernel(float* __restrict__ extout, int M, int layer) {
    int node = blockIdx.x * 8 + (threadIdx.x >> 5);
    if (node >= M) return;
    int lane = threadIdx.x & 31;
    int beg = node ? __ldg(&g_rowstart[node - 1]) : 0;
    int end = __ldg(&g_rowstart[node]);
    const uint2* Yh = (const uint2*)g_Yh;   // 32 uint2 per row
    const uint2* Rh = (const uint2*)g_Rh[layer];
    float4 acc = make_float4(0.f, 0.f, 0.f, 0.f);
    int i = beg;
    for (; i + 1 < end; i += 2) {
        int e0 = __ldg(&g_edata[i]);
        int e1 = __ldg(&g_edata[i + 1]);
        uint2 y0 = __ldg(&Yh[(size_t)(e0 >> 8) * 32 + lane]);
        uint2 r0 = __ldg(&Rh[(size_t)(e0 & 255) * 32 + lane]);
        uint2 y1 = __ldg(&Yh[(size_t)(e1 >> 8) * 32 + lane]);
        uint2 r1 = __ldg(&Rh[(size_t)(e1 & 255) * 32 + lane]);
        float2 ya = __half22float2(*(__half2*)&y0.x), yb = __half22float2(*(__half2*)&y0.y);
        float2 ra = __half22float2(*(__half2*)&r0.x), rb = __half22float2(*(__half2*)&r0.y);
        float2 yc = __half22float2(*(__half2*)&y1.x), yd = __half22float2(*(__half2*)&y1.y);
        float2 rc = __half22float2(*(__half2*)&r1.x), rd = __half22float2(*(__half2*)&r1.y);
        acc.x += (ya.x - ra.x) + (yc.x - rc.x);
        acc.y += (ya.y - ra.y) + (yc.y - rc.y);
        acc.z += (yb.x - rb.x) + (yd.x - rd.x);
        acc.w += (yb.y - rb.y) + (yd.y - rd.y);
    }
    if (i < end) {
        int e0 = __ldg(&g_edata[i]);
        uint2 y0 = __ldg(&Yh[(size_t)(e0 >> 8) * 32 + lane]);
        uint2 r0 = __ldg(&Rh[(size_t)(e0 & 255) * 32 + lane]);
        float2 ya = __half22float2(*(__half2*)&y0.x), yb = __half22float2(*(__half2*)&y0.y);
        float2 ra = __half22float2(*(__half2*)&r0.x), rb = __half22float2(*(__half2*)&r0.y);
        acc.x += ya.x - ra.x;
        acc.y += ya.y - ra.y;
        acc.z += yb.x - rb.x;
        acc.w += yb.y - rb.y;
    }
    float* H = TO_OUT ? extout : g_H;
    int off = lane * 4;
    float4 h = *(float4*)&H[(size_t)node * DD + off];
    h.x += acc.x; h.y += acc.y; h.z += acc.z; h.w += acc.w;
    *(float4*)&H[(size_t)node * DD + off] = h;
}

// ---------------------------------------------------------------------------
extern "C" void kernel_launch(void* const* d_in, const int* in_sizes, int n_in,
                              void* d_out, int out_size) {
    const float* x    = (const float*)d_in[0];
    const int*   ei   = (const int*)d_in[1];
    const int*   et   = (const int*)d_in[2];
    const float* W_I1 = (const float*)d_in[3];
    const float* W_O1 = (const float*)d_in[4];
    const float* rel1 = (const float*)d_in[5];
    const float* b1   = (const float*)d_in[6];
    const float* W_I2 = (const float*)d_in[7];
    const float* W_O2 = (const float*)d_in[8];
    const float* rel2 = (const float*)d_in[9];
    const float* b2   = (const float*)d_in[10];
    float* out = (float*)d_out;

    int M = in_sizes[0] / DD;      // 50000
    int E = in_sizes[2];           // 800000
    const int* src = ei;
    const int* dst = ei + E;

    // lazily-created side stream + events (created on the uncaptured
    // correctness call; no device memory involved)
    static cudaStream_t s2 = nullptr;
    static cudaEvent_t evFork = nullptr, evJoin = nullptr;
    if (!s2) {
        cudaStreamCreateWithFlags(&s2, cudaStreamNonBlocking);
        cudaEventCreateWithFlags(&evFork, cudaEventDisableTiming);
        cudaEventCreateWithFlags(&evJoin, cudaEventDisableTiming);
    }

    cudaFuncSetAttribute(gemm_mma_kernel<false, false, false>,
                         cudaFuncAttributeMaxDynamicSharedMemorySize, SM_BYTES);
    cudaFuncSetAttribute(gemm_mma_kernel<true, true, true>,
                         cudaFuncAttributeMaxDynamicSharedMemorySize, SM_BYTES);

    dim3 ggemm((M + 63) / 64, 2);
    int gath_blocks = (M + 7) / 8;

    // ---- fork: CSR build on side stream (only gathers depend on it) ----
    cudaEventRecord(evFork, 0);
    cudaStreamWaitEvent(s2, evFork, 0);
    zero_kernel<<<(M + 255) / 256, 256, 0, s2>>>(M);
    hist_kernel<<<(E + 255) / 256, 256, 0, s2>>>(dst, E);
    scan_kernel<<<1, 1024, 0, s2>>>(M);
    fill_kernel<<<(E + 255) / 256, 256, 0, s2>>>(src, dst, et, E);
    cudaEventRecord(evJoin, s2);

    // ---- main stream: layer-1 GEMM chain (independent of CSR) ----
    packb_kernel<<<(256 * DD + 255) / 256, 256>>>(W_I1, W_O1);
    relgemm_kernel<<<NRELMX, DD>>>(rel1, W_I1, 0);
    gemm_mma_kernel<false, false, false><<<ggemm, 256, SM_BYTES>>>(x, b1, nullptr, M, 0);

    // layer-2 weight prep (writes layer-2 buffers: B image + R[1])
    packb_kernel<<<(256 * DD + 255) / 256, 256>>>(W_I2, W_O2);
    relgemm_kernel<<<NRELMX, DD>>>(rel2, W_I2, 1);

    // ---- join CSR, then gathers / layer-2 GEMM ----
    cudaStreamWaitEvent(0, evJoin, 0);
    gather_kernel<false><<<gath_blocks, 256>>>(nullptr, M, 0);
    gemm_mma_kernel<true, true, true><<<ggemm, 256, SM_BYTES>>>(nullptr, b2, out, M, 1);
    gather_kernel<true><<<gath_blocks, 256>>>(out, M, 1);
}